// round 12
// baseline (speedup 1.0000x reference)
#include <cuda_runtime.h>
#include <cuda_bf16.h>
#include <cuda_fp16.h>
#include <cstdint>

#define LEAKY 0.2f
#define BN_EPS 1e-5f
#define MAXN 50000
#define MAXE 1600000
#define MAXET (MAXN + MAXE)
#define SCAN_N 50176
#define NBLK 196
#define NSM 148
#define BNR_MAX_BLOCKS (NSM * 4)

// ---------------- device scratch ----------------
__device__ int   g_deg[SCAN_N];
__device__ int   g_off[MAXN + 1];
__device__ int   g_cursor[MAXN];
__device__ int   g_csr[MAXET];
__device__ int   g_bsum[256];
__device__ float g_red[BNR_MAX_BLOCKS * 256];
__device__ float g_scale[128];
__device__ float g_shift[128];
__device__ float g_HW[MAXN * 2];        // layer-3 head features (fp32)
__device__ __half g_HWh[MAXN * 128];    // layer-1/2 head features (fp16 gather payload)
__device__ float g_HL[MAXN * 128];
__device__ float2 g_ESDs[MAXN];         // per-src attention terms (es0, es1)
__device__ float2 g_ESDd[MAXN];         // per-dst attention terms (ed0, ed1)
__device__ float g_H[MAXN * 128];
// double-buffered per-layer weights
__device__ __nv_bfloat16 g_Bhi[2][256 * 128];   // [n][k]
__device__ __nv_bfloat16 g_Blo[2][256 * 128];
__device__ float g_bcatL[2][256];
__device__ float g_wesd[2][512];                // [k][4]

// ---------------- software grid barriers (separate slots: bnr vs csr) --------------
__device__ unsigned g_bcount = 0, g_bgen = 0;      // k_bnr
__device__ unsigned g_ccount = 0, g_cgen = 0;      // k_csr

__device__ __forceinline__ void grid_sync_slot(unsigned* cnt, unsigned* gen, int nb) {
    __syncthreads();
    if (threadIdx.x == 0) {
        unsigned my = *((volatile unsigned*)gen);
        __threadfence();
        unsigned old = atomicAdd(cnt, 1);
        if (old == (unsigned)nb - 1) {
            *cnt = 0;
            __threadfence();
            atomicAdd(gen, 1);
        } else {
            while (*((volatile unsigned*)gen) == my) { __nanosleep(64); }
            __threadfence();
        }
    }
    __syncthreads();
}

// ---------------- kernel: CSR build (persistent, dedicated barrier) ----------------
__global__ __launch_bounds__(256) void k_csr(const int* __restrict__ ei, int E, int ET,
                                             int n, int nb) {
    __shared__ int sh[256];
    int tid = threadIdx.x, bid = blockIdx.x;
    int gsz = nb * 256, gtid = bid * 256 + tid;

    for (int i = gtid; i < SCAN_N; i += gsz) g_deg[i] = 0;
    grid_sync_slot(&g_ccount, &g_cgen, nb);

    for (int i = gtid; i < ET; i += gsz) {
        int d = (i < E) ? ei[E + i] : (i - E);
        atomicAdd(&g_deg[d], 1);
    }
    grid_sync_slot(&g_ccount, &g_cgen, nb);

    for (int b = bid; b < NBLK; b += nb) {
        sh[tid] = g_deg[b * 256 + tid];
        __syncthreads();
        for (int o = 128; o > 0; o >>= 1) {
            if (tid < o) sh[tid] += sh[tid + o];
            __syncthreads();
        }
        if (tid == 0) g_bsum[b] = sh[0];
        __syncthreads();
    }
    grid_sync_slot(&g_ccount, &g_cgen, nb);

    if (bid == 0) {
        int v = (tid < NBLK) ? g_bsum[tid] : 0;
        sh[tid] = v;
        __syncthreads();
        for (int o = 1; o < 256; o <<= 1) {
            int t = (tid >= o) ? sh[tid - o] : 0;
            __syncthreads();
            sh[tid] += t;
            __syncthreads();
        }
        if (tid < NBLK) g_bsum[tid] = sh[tid] - v;
    }
    grid_sync_slot(&g_ccount, &g_cgen, nb);

    for (int b = bid; b < NBLK; b += nb) {
        int gi = b * 256 + tid;
        int v = g_deg[gi];
        sh[tid] = v;
        __syncthreads();
        for (int o = 1; o < 256; o <<= 1) {
            int t = (tid >= o) ? sh[tid - o] : 0;
            __syncthreads();
            sh[tid] += t;
            __syncthreads();
        }
        int ex = sh[tid] - v + g_bsum[b];
        if (gi <= n) g_off[gi] = ex;
        if (gi < n)  g_cursor[gi] = ex;
        __syncthreads();
    }
    grid_sync_slot(&g_ccount, &g_cgen, nb);

    for (int i = gtid; i < ET; i += gsz) {
        int s, d;
        if (i < E) { s = ei[i]; d = ei[E + i]; }
        else       { s = d = i - E; }
        g_csr[atomicAdd(&g_cursor[d], 1)] = s;
    }
}

// ---------------- BN stats: float4 streaming, multi-CTA/SM, grid_sync, final -------
// Channel invariant: stride nb*256 float4s ≡ 0 mod 32, so thread tid's channel
// group is fixed: 4*(tid & 31) .. +3.
__global__ __launch_bounds__(256) void k_bnr(const float* __restrict__ A, int total,
                                             const float* __restrict__ bg,
                                             const float* __restrict__ bb,
                                             float inv_n, int nb) {
    const float4* H4 = (const float4*)(A ? A : g_H);
    __shared__ float4 ss[256], qq[256];
    int tid = threadIdx.x, bid = blockIdx.x;
    int total4 = total >> 2;
    float4 s = {0.f, 0.f, 0.f, 0.f}, q = {0.f, 0.f, 0.f, 0.f};
    for (int e = bid * 256 + tid; e < total4; e += nb * 256) {
        float4 v = H4[e];
        s.x += v.x; s.y += v.y; s.z += v.z; s.w += v.w;
        q.x += v.x * v.x; q.y += v.y * v.y; q.z += v.z * v.z; q.w += v.w * v.w;
    }
    ss[tid] = s; qq[tid] = q;
    __syncthreads();
    if (tid < 32) {
        float4 S = ss[tid], Q = qq[tid];
        for (int t = tid + 32; t < 256; t += 32) {
            float4 a = ss[t], b = qq[t];
            S.x += a.x; S.y += a.y; S.z += a.z; S.w += a.w;
            Q.x += b.x; Q.y += b.y; Q.z += b.z; Q.w += b.w;
        }
        int c = tid * 4;
        g_red[bid * 256 + c]     = S.x;
        g_red[bid * 256 + c + 1] = S.y;
        g_red[bid * 256 + c + 2] = S.z;
        g_red[bid * 256 + c + 3] = S.w;
        g_red[bid * 256 + 128 + c]     = Q.x;
        g_red[bid * 256 + 128 + c + 1] = Q.y;
        g_red[bid * 256 + 128 + c + 2] = Q.z;
        g_red[bid * 256 + 128 + c + 3] = Q.w;
    }
    grid_sync_slot(&g_bcount, &g_bgen, nb);
    if (bid == 0 && tid < 128) {
        float s2 = 0.f, q2 = 0.f;
        for (int b = 0; b < nb; b++) {
            s2 += g_red[b * 256 + tid];
            q2 += g_red[b * 256 + 128 + tid];
        }
        float mu  = s2 * inv_n;
        float var = q2 * inv_n - mu * mu;
        float sc  = bg[tid] * rsqrtf(var + BN_EPS);
        g_scale[tid] = sc;
        g_shift[tid] = bb[tid] - mu * sc;
    }
}

// ---------------- weight prep (side stream, data-independent) ----------------
__global__ void k_prep12(int l, const float* __restrict__ W, const float* __restrict__ lw,
                         const float* __restrict__ lb, const float* __restrict__ as,
                         const float* __restrict__ ad) {
    int idx = blockIdx.x * 256 + threadIdx.x;
    if (idx >= 128 * 260) return;
    int k = idx / 260, j = idx % 260;
    float v;
    if (j < 128)       v = W[k * 128 + j];
    else if (j < 256)  v = lw[k * 128 + (j - 128)];
    else {
        int t = j - 256;
        int hh = t & 1;
        const float* a = (t < 2) ? as : ad;
        float s = 0.f;
        for (int f = 0; f < 64; f++) s += W[k * 128 + hh * 64 + f] * a[hh * 64 + f];
        v = s;
    }
    if (j < 256) {
        __nv_bfloat16 h = __float2bfloat16(v);
        g_Bhi[l][j * 128 + k] = h;
        g_Blo[l][j * 128 + k] = __float2bfloat16(v - __bfloat162float(h));
        if (k == 0) g_bcatL[l][j] = (j >= 128) ? lb[j - 128] : 0.f;
    } else {
        g_wesd[l][k * 4 + (j - 256)] = v;
    }
}

// ---------------- mma helpers ----------------
__device__ __forceinline__ uint32_t smem_u32(const void* p) {
    uint32_t a;
    asm("{ .reg .u64 t; cvta.to.shared.u64 t, %1; cvt.u32.u64 %0, t; }" : "=r"(a) : "l"(p));
    return a;
}
__device__ __forceinline__ void ldsm_x4(uint32_t* r, uint32_t addr) {
    asm volatile("ldmatrix.sync.aligned.m8n8.x4.shared.b16 {%0,%1,%2,%3}, [%4];"
        : "=r"(r[0]), "=r"(r[1]), "=r"(r[2]), "=r"(r[3]) : "r"(addr));
}
__device__ __forceinline__ void ldsm_x2(uint32_t* r, uint32_t addr) {
    asm volatile("ldmatrix.sync.aligned.m8n8.x2.shared.b16 {%0,%1}, [%2];"
        : "=r"(r[0]), "=r"(r[1]) : "r"(addr));
}
__device__ __forceinline__ void mma_bf16(float* d, const uint32_t* a, const uint32_t* b) {
    asm volatile("mma.sync.aligned.m16n8k16.row.col.f32.bf16.bf16.f32 "
        "{%0,%1,%2,%3}, {%4,%5,%6,%7}, {%8,%9}, {%0,%1,%2,%3};"
        : "+f"(d[0]), "+f"(d[1]), "+f"(d[2]), "+f"(d[3])
        : "r"(a[0]), "r"(a[1]), "r"(a[2]), "r"(a[3]), "r"(b[0]), "r"(b[1]));
}
__device__ __forceinline__ float leaky(float x) { return (x > 0.f) ? x : LEAKY * x; }

// ---------------- tensor-core GEMM + fused esd ----------------
#define APAD 136
#define TILE_BYTES (128 * APAD * 2)
#define GEMM_SMEM  (4 * TILE_BYTES + 2048)

__global__ __launch_bounds__(256, 1) void k_gemm_mma(int l, const float* __restrict__ Ain, int M) {
    const float* A = Ain ? Ain : g_H;
    extern __shared__ char sm[];
    __nv_bfloat16* sAhi = (__nv_bfloat16*)sm;
    __nv_bfloat16* sAlo = (__nv_bfloat16*)(sm + TILE_BYTES);
    __nv_bfloat16* sBhi = (__nv_bfloat16*)(sm + 2 * TILE_BYTES);
    __nv_bfloat16* sBlo = (__nv_bfloat16*)(sm + 3 * TILE_BYTES);
    float* wesd = (float*)(sm + 4 * TILE_BYTES);

    int tid = threadIdx.x, lane = tid & 31, wid = tid >> 5;
    int warp_m = wid & 1;
    int warp_n = wid >> 1;
    int m0 = blockIdx.x * 128;
    int n0 = blockIdx.y * 128;

    for (int idx = tid; idx < 4096; idx += 256) {
        int row = idx >> 5, c = (idx & 31) * 4;
        int gm = m0 + row;
        float4 t = (gm < M) ? *(const float4*)(A + gm * 128 + c)
                            : make_float4(0.f, 0.f, 0.f, 0.f);
        float v0 = t.x * g_scale[c]     + g_shift[c];
        float v1 = t.y * g_scale[c + 1] + g_shift[c + 1];
        float v2 = t.z * g_scale[c + 2] + g_shift[c + 2];
        float v3 = t.w * g_scale[c + 3] + g_shift[c + 3];
        if (gm >= M) { v0 = v1 = v2 = v3 = 0.f; }
        __nv_bfloat16 h0 = __float2bfloat16(v0), h1 = __float2bfloat16(v1);
        __nv_bfloat16 h2 = __float2bfloat16(v2), h3 = __float2bfloat16(v3);
        __nv_bfloat162 hp0(h0, h1), hp1(h2, h3);
        __nv_bfloat162 lp0(__float2bfloat16(v0 - __bfloat162float(h0)),
                           __float2bfloat16(v1 - __bfloat162float(h1)));
        __nv_bfloat162 lp1(__float2bfloat16(v2 - __bfloat162float(h2)),
                           __float2bfloat16(v3 - __bfloat162float(h3)));
        int o = row * APAD + c;
        *(__nv_bfloat162*)(sAhi + o)     = hp0;
        *(__nv_bfloat162*)(sAhi + o + 2) = hp1;
        *(__nv_bfloat162*)(sAlo + o)     = lp0;
        *(__nv_bfloat162*)(sAlo + o + 2) = lp1;
    }
    for (int idx = tid; idx < 2048; idx += 256) {
        int row = idx >> 4, c = (idx & 15) * 8;
        int gn = n0 + row;
        uint4 hv = *(const uint4*)(g_Bhi[l] + gn * 128 + c);
        uint4 lv = *(const uint4*)(g_Blo[l] + gn * 128 + c);
        int o = row * APAD + c;
        *(uint4*)(sBhi + o) = hv;
        *(uint4*)(sBlo + o) = lv;
    }
    if (blockIdx.y == 1)
        for (int i = tid; i < 512; i += 256) wesd[i] = g_wesd[l][i];
    __syncthreads();

    int rA = lane & 15, cA = (lane >> 4) * 8;
    int rB = lane & 7,  cB = ((lane >> 3) & 1) * 8;
    uint32_t baseAhi[4], baseAlo[4], baseBhi[4], baseBlo[4];
#pragma unroll
    for (int mt = 0; mt < 4; mt++) {
        int row = warp_m * 64 + mt * 16 + rA;
        baseAhi[mt] = smem_u32(sAhi + row * APAD + cA);
        baseAlo[mt] = smem_u32(sAlo + row * APAD + cA);
    }
#pragma unroll
    for (int nt = 0; nt < 4; nt++) {
        int row = warp_n * 32 + nt * 8 + rB;
        baseBhi[nt] = smem_u32(sBhi + row * APAD + cB);
        baseBlo[nt] = smem_u32(sBlo + row * APAD + cB);
    }

    float acc[4][4][4] = {};
#pragma unroll
    for (int ks = 0; ks < 8; ks++) {
        uint32_t koff = ks * 32;
        uint32_t ahi[4][4], alo[4][4], bhi[4][2], blo[4][2];
#pragma unroll
        for (int mt = 0; mt < 4; mt++) {
            ldsm_x4(ahi[mt], baseAhi[mt] + koff);
            ldsm_x4(alo[mt], baseAlo[mt] + koff);
        }
#pragma unroll
        for (int nt = 0; nt < 4; nt++) {
            ldsm_x2(bhi[nt], baseBhi[nt] + koff);
            ldsm_x2(blo[nt], baseBlo[nt] + koff);
        }
#pragma unroll
        for (int mt = 0; mt < 4; mt++)
#pragma unroll
            for (int nt = 0; nt < 4; nt++) {
                mma_bf16(acc[mt][nt], ahi[mt], bhi[nt]);
                mma_bf16(acc[mt][nt], ahi[mt], blo[nt]);
                mma_bf16(acc[mt][nt], alo[mt], bhi[nt]);
            }
    }

    // ---- epilogue ----
#pragma unroll
    for (int mt = 0; mt < 4; mt++) {
        int gm0 = m0 + warp_m * 64 + mt * 16 + (lane >> 2);
#pragma unroll
        for (int nt = 0; nt < 4; nt++) {
            int col = warp_n * 32 + nt * 8 + (lane & 3) * 2;
            float b0 = g_bcatL[l][n0 + col], b1 = g_bcatL[l][n0 + col + 1];
            if (blockIdx.y == 0) {
                if (gm0 < M)
                    *(__half2*)(g_HWh + gm0 * 128 + col) =
                        __floats2half2_rn(acc[mt][nt][0] + b0, acc[mt][nt][1] + b1);
                if (gm0 + 8 < M)
                    *(__half2*)(g_HWh + (gm0 + 8) * 128 + col) =
                        __floats2half2_rn(acc[mt][nt][2] + b0, acc[mt][nt][3] + b1);
            } else {
                if (gm0 < M) {
                    float2 v = {acc[mt][nt][0] + b0, acc[mt][nt][1] + b1};
                    *(float2*)(g_HL + gm0 * 128 + col) = v;
                }
                if (gm0 + 8 < M) {
                    float2 v = {acc[mt][nt][2] + b0, acc[mt][nt][3] + b1};
                    *(float2*)(g_HL + (gm0 + 8) * 128 + col) = v;
                }
            }
        }
    }

    if (blockIdx.y == 1) {
        for (int r = 0; r < 16; r++) {
            int row = wid * 16 + r;
            int gm = m0 + row;
            int k = lane * 4;
            int o = row * APAD + k;
            float a0 = __bfloat162float(sAhi[o])     + __bfloat162float(sAlo[o]);
            float a1 = __bfloat162float(sAhi[o + 1]) + __bfloat162float(sAlo[o + 1]);
            float a2 = __bfloat162float(sAhi[o + 2]) + __bfloat162float(sAlo[o + 2]);
            float a3 = __bfloat162float(sAhi[o + 3]) + __bfloat162float(sAlo[o + 3]);
            float s0 = a0 * wesd[k * 4]     + a1 * wesd[(k + 1) * 4]     + a2 * wesd[(k + 2) * 4]     + a3 * wesd[(k + 3) * 4];
            float s1 = a0 * wesd[k * 4 + 1] + a1 * wesd[(k + 1) * 4 + 1] + a2 * wesd[(k + 2) * 4 + 1] + a3 * wesd[(k + 3) * 4 + 1];
            float s2 = a0 * wesd[k * 4 + 2] + a1 * wesd[(k + 1) * 4 + 2] + a2 * wesd[(k + 2) * 4 + 2] + a3 * wesd[(k + 3) * 4 + 2];
            float s3 = a0 * wesd[k * 4 + 3] + a1 * wesd[(k + 1) * 4 + 3] + a2 * wesd[(k + 2) * 4 + 3] + a3 * wesd[(k + 3) * 4 + 3];
#pragma unroll
            for (int sh = 16; sh > 0; sh >>= 1) {
                s0 += __shfl_xor_sync(0xffffffffu, s0, sh);
                s1 += __shfl_xor_sync(0xffffffffu, s1, sh);
                s2 += __shfl_xor_sync(0xffffffffu, s2, sh);
                s3 += __shfl_xor_sync(0xffffffffu, s3, sh);
            }
            if (lane == 0 && gm < M) {
                g_ESDs[gm] = make_float2(s0, s1);
                g_ESDd[gm] = make_float2(s2, s3);
            }
        }
    }
}

// ---------------- layer 3 GEMV (self-prep weights) ----------------
__global__ __launch_bounds__(256) void k_gemv6(const float* __restrict__ W3,
                                               const float* __restrict__ lw3,
                                               const float* __restrict__ lb3,
                                               const float* __restrict__ as3,
                                               const float* __restrict__ ad3,
                                               int n) {
    const float* A = g_H;
    __shared__ float ws[768];
    __shared__ float bs[8];
    int tid = threadIdx.x;
    for (int i = tid; i < 768; i += 256) {
        int k = i / 6, j = i % 6;
        float v;
        if (j < 2)      v = W3[k * 2 + j];
        else if (j < 4) v = lw3[k * 2 + (j - 2)];
        else {
            const float* a = (j == 4) ? as3 : ad3;
            v = W3[k * 2] * a[0] + W3[k * 2 + 1] * a[1];
        }
        ws[i] = v;
    }
    if (tid < 2) bs[tid] = lb3[tid];
    __syncthreads();
    int row = blockIdx.x * 8 + (tid >> 5);
    int lane = tid & 31;
    if (row >= n) return;
    float4 a = ((const float4*)A)[row * 32 + lane];
    int k = lane * 4;
    float a0 = a.x * g_scale[k]     + g_shift[k];
    float a1 = a.y * g_scale[k + 1] + g_shift[k + 1];
    float a2 = a.z * g_scale[k + 2] + g_shift[k + 2];
    float a3 = a.w * g_scale[k + 3] + g_shift[k + 3];
    float c[6];
#pragma unroll
    for (int j = 0; j < 6; j++)
        c[j] = a0 * ws[k * 6 + j] + a1 * ws[(k + 1) * 6 + j] +
               a2 * ws[(k + 2) * 6 + j] + a3 * ws[(k + 3) * 6 + j];
#pragma unroll
    for (int j = 0; j < 6; j++)
#pragma unroll
        for (int o = 16; o > 0; o >>= 1) c[j] += __shfl_xor_sync(0xffffffffu, c[j], o);
    if (lane == 0) {
        g_HW[row * 2]     = c[0];
        g_HW[row * 2 + 1] = c[1];
        g_HL[row * 2]     = c[2] + bs[0];
        g_HL[row * 2 + 1] = c[3] + bs[1];
        g_ESDs[row] = make_float2(c[4], 0.f);
        g_ESDd[row] = make_float2(c[5], 0.f);
    }
}

// ---------------- GAT edge phase, layers 1/2 (single-pass, fp16 gather) ----------------
__global__ __launch_bounds__(256) void k_gat_edge12(const float* __restrict__ gb, int n) {
    int warp = (blockIdx.x * 256 + threadIdx.x) >> 5;
    int lane = threadIdx.x & 31;
    if (warp >= n) return;
    int node = warp;
    int beg = g_off[node], end = g_off[node + 1];
    float2 ed = g_ESDd[node];
    const uint2* HWh2 = (const uint2*)g_HWh;

    float sum0 = 0.f, sum1 = 0.f;
    float ax = 0.f, ay = 0.f, az = 0.f, aw = 0.f;
    for (int base = beg; base < end; base += 32) {
        int i = base + lane;
        int s = 0;
        float p0 = 0.f, p1 = 0.f;
        if (i < end) {
            s = g_csr[i];
            float2 e = g_ESDs[s];
            p0 = __expf(leaky(e.x + ed.x));
            p1 = __expf(leaky(e.y + ed.y));
        }
        sum0 += p0; sum1 += p1;
        int cnt = min(32, end - base);
        if (cnt == 32) {
#pragma unroll
            for (int j = 0; j < 32; j++) {
                int sj   = __shfl_sync(0xffffffffu, s, j);
                float q0 = __shfl_sync(0xffffffffu, p0, j);
                float q1 = __shfl_sync(0xffffffffu, p1, j);
                float ph = (lane < 16) ? q0 : q1;
                uint2 hv = HWh2[sj * 32 + lane];
                float2 f01 = __half22float2(*(__half2*)&hv.x);
                float2 f23 = __half22float2(*(__half2*)&hv.y);
                ax += ph * f01.x; ay += ph * f01.y; az += ph * f23.x; aw += ph * f23.y;
            }
        } else {
            for (int j = 0; j < cnt; j++) {
                int sj   = __shfl_sync(0xffffffffu, s, j);
                float q0 = __shfl_sync(0xffffffffu, p0, j);
                float q1 = __shfl_sync(0xffffffffu, p1, j);
                float ph = (lane < 16) ? q0 : q1;
                uint2 hv = HWh2[sj * 32 + lane];
                float2 f01 = __half22float2(*(__half2*)&hv.x);
                float2 f23 = __half22float2(*(__half2*)&hv.y);
                ax += ph * f01.x; ay += ph * f01.y; az += ph * f23.x; aw += ph * f23.y;
            }
        }
    }
#pragma unroll
    for (int o = 16; o > 0; o >>= 1) {
        sum0 += __shfl_xor_sync(0xffffffffu, sum0, o);
        sum1 += __shfl_xor_sync(0xffffffffu, sum1, o);
    }
    float inv = 1.f / ((lane < 16) ? sum0 : sum1);

    float4 hl = ((const float4*)g_HL)[node * 32 + lane];
    float4 gv = ((const float4*)gb)[lane];
    float4 o4;
    o4.x = fmaxf(hl.x + gv.x + ax * inv, 0.f);
    o4.y = fmaxf(hl.y + gv.y + ay * inv, 0.f);
    o4.z = fmaxf(hl.z + gv.z + az * inv, 0.f);
    o4.w = fmaxf(hl.w + gv.w + aw * inv, 0.f);
    ((float4*)g_H)[node * 32 + lane] = o4;
}

// ---------------- GAT edge phase, layer 3 (single-pass) ----------------
__global__ __launch_bounds__(256) void k_gat_edge3(const float* __restrict__ gb3,
                                                   float* __restrict__ out, int n) {
    int warp = (blockIdx.x * 256 + threadIdx.x) >> 5;
    int lane = threadIdx.x & 31;
    if (warp >= n) return;
    int node = warp;
    int beg = g_off[node], end = g_off[node + 1];
    float edv = g_ESDd[node].x;
    const float2* HW2 = (const float2*)g_HW;

    float sum = 0.f, a0 = 0.f, a1 = 0.f;
    for (int i = beg + lane; i < end; i += 32) {
        int s = g_csr[i];
        float p = __expf(leaky(g_ESDs[s].x + edv));
        float2 h = HW2[s];
        sum += p;
        a0 += p * h.x;
        a1 += p * h.y;
    }
#pragma unroll
    for (int o = 16; o > 0; o >>= 1) {
        sum += __shfl_xor_sync(0xffffffffu, sum, o);
        a0  += __shfl_xor_sync(0xffffffffu, a0, o);
        a1  += __shfl_xor_sync(0xffffffffu, a1, o);
    }
    if (lane == 0) {
        float inv = 1.f / sum;
        out[node * 2]     = fmaxf(g_HL[node * 2]     + gb3[0] + a0 * inv, 0.f);
        out[node * 2 + 1] = fmaxf(g_HL[node * 2 + 1] + gb3[1] + a1 * inv, 0.f);
    }
}

// ---------------- host launch ----------------
extern "C" void kernel_launch(void* const* d_in, const int* in_sizes, int n_in,
                              void* d_out, int out_size) {
    const float* x  = (const float*)d_in[0];
    const int*   ei = (const int*)d_in[1];
    const float *W1 = (const float*)d_in[2],  *as1 = (const float*)d_in[3],
                *ad1 = (const float*)d_in[4], *gb1 = (const float*)d_in[5],
                *lw1 = (const float*)d_in[6], *lb1 = (const float*)d_in[7],
                *bg1 = (const float*)d_in[8], *bb1 = (const float*)d_in[9];
    const float *W2 = (const float*)d_in[10], *as2 = (const float*)d_in[11],
                *ad2 = (const float*)d_in[12], *gb2 = (const float*)d_in[13],
                *lw2 = (const float*)d_in[14], *lb2 = (const float*)d_in[15],
                *bg2 = (const float*)d_in[16], *bb2 = (const float*)d_in[17];
    const float *W3 = (const float*)d_in[18], *as3 = (const float*)d_in[19],
                *ad3 = (const float*)d_in[20], *gb3 = (const float*)d_in[21],
                *lw3 = (const float*)d_in[22], *lb3 = (const float*)d_in[23],
                *bg3 = (const float*)d_in[24], *bb3 = (const float*)d_in[25];
    (void)n_in; (void)out_size;

    int n  = in_sizes[0] / 128;
    int E  = in_sizes[1] / 2;
    int ET = E + n;
    float* out = (float*)d_out;
    float inv_n = 1.f / (float)n;

    dim3 gg((n + 127) / 128, 2);
    int wb = (n + 7) / 8;

    static int inited = 0;
    static int nb_bnr = NSM;
    static cudaStream_t s1 = nullptr, s2 = nullptr;
    static cudaEvent_t ev_fork = nullptr, ev_p1 = nullptr, ev_p2 = nullptr, ev_csr = nullptr;
    if (!inited) {
        cudaFuncSetAttribute(k_gemm_mma, cudaFuncAttributeMaxDynamicSharedMemorySize, GEMM_SMEM);
        cudaStreamCreateWithFlags(&s1, cudaStreamNonBlocking);
        cudaStreamCreateWithFlags(&s2, cudaStreamNonBlocking);
        cudaEventCreateWithFlags(&ev_fork, cudaEventDisableTiming);
        cudaEventCreateWithFlags(&ev_p1, cudaEventDisableTiming);
        cudaEventCreateWithFlags(&ev_p2, cudaEventDisableTiming);
        cudaEventCreateWithFlags(&ev_csr, cudaEventDisableTiming);
        int nsm = 0, maxb = 1;
        cudaDeviceGetAttribute(&nsm, cudaDevAttrMultiProcessorCount, 0);
        if (nsm > NSM) nsm = NSM;
        cudaOccupancyMaxActiveBlocksPerMultiprocessor(&maxb, k_bnr, 256, 0);
        if (maxb > 4) maxb = 4;
        if (maxb < 1) maxb = 1;
        nb_bnr = nsm * maxb;
        if (nb_bnr > BNR_MAX_BLOCKS) nb_bnr = BNR_MAX_BLOCKS;
        inited = 1;
    }

    // ---- fork side work ----
    cudaEventRecord(ev_fork, 0);
    cudaStreamWaitEvent(s1, ev_fork, 0);
    cudaStreamWaitEvent(s2, ev_fork, 0);

    // weight preps (s1)
    k_prep12<<<131, 256, 0, s1>>>(0, W1, lw1, lb1, as1, ad1);
    cudaEventRecord(ev_p1, s1);
    k_prep12<<<131, 256, 0, s1>>>(1, W2, lw2, lb2, as2, ad2);
    cudaEventRecord(ev_p2, s1);

    // CSR build (s2, single persistent kernel)
    k_csr<<<NSM, 256, 0, s2>>>(ei, E, ET, n, NSM);
    cudaEventRecord(ev_csr, s2);

    // ---- main chain ----
    k_bnr<<<nb_bnr, 256>>>(x, n * 128, bg1, bb1, inv_n, nb_bnr);
    cudaStreamWaitEvent(0, ev_p1, 0);
    k_gemm_mma<<<gg, 256, GEMM_SMEM>>>(0, x, n);
    cudaStreamWaitEvent(0, ev_csr, 0);
    k_gat_edge12<<<wb, 256>>>(gb1, n);

    k_bnr<<<nb_bnr, 256>>>(nullptr, n * 128, bg2, bb2, inv_n, nb_bnr);
    cudaStreamWaitEvent(0, ev_p2, 0);
    k_gemm_mma<<<gg, 256, GEMM_SMEM>>>(1, nullptr, n);
    k_gat_edge12<<<wb, 256>>>(gb2, n);

    k_bnr<<<nb_bnr, 256>>>(nullptr, n * 128, bg3, bb3, inv_n, nb_bnr);
    k_gemv6<<<wb, 256>>>(W3, lw3, lb3, as3, ad3, n);
    k_gat_edge3<<<wb, 256>>>(gb3, out, n);
}

// round 13
// speedup vs baseline: 1.0002x; 1.0002x over previous
#include <cuda_runtime.h>
#include <cuda_bf16.h>
#include <cuda_fp16.h>
#include <cstdint>

#define LEAKY 0.2f
#define BN_EPS 1e-5f
#define MAXN 50000
#define MAXE 1600000
#define MAXET (MAXN + MAXE)
#define SCAN_N 50176
#define NBLK 196
#define NSM 148

// ---------------- device scratch ----------------
__device__ int   g_deg[SCAN_N];
__device__ int   g_off[MAXN + 1];
__device__ int   g_cursor[MAXN];
__device__ int   g_csr[MAXET];
__device__ int   g_bsum[256];
__device__ float g_red[NSM * 256];
__device__ float g_scale[128];
__device__ float g_shift[128];
__device__ float g_HW[MAXN * 2];        // layer-3 head features (fp32)
__device__ __half g_HWh[MAXN * 128];    // layer-1/2 head features (fp16 gather payload)
__device__ float g_HL[MAXN * 128];
__device__ float2 g_ESDs[MAXN];         // per-src attention terms (es0, es1)
__device__ float2 g_ESDd[MAXN];         // per-dst attention terms (ed0, ed1)
__device__ float g_H[MAXN * 128];
// double-buffered per-layer weights
__device__ __nv_bfloat16 g_Bhi[2][256 * 128];   // [n][k]
__device__ __nv_bfloat16 g_Blo[2][256 * 128];
__device__ float g_bcatL[2][256];
__device__ float g_wesd[2][512];                // [k][4]

// ---------------- software grid barriers (separate slots: bnr vs csr) --------------
__device__ unsigned g_bcount = 0, g_bgen = 0;      // k_bnr
__device__ unsigned g_ccount = 0, g_cgen = 0;      // k_csr

__device__ __forceinline__ void grid_sync_slot(unsigned* cnt, unsigned* gen, int nb) {
    __syncthreads();
    if (threadIdx.x == 0) {
        unsigned my = *((volatile unsigned*)gen);
        __threadfence();
        unsigned old = atomicAdd(cnt, 1);
        if (old == (unsigned)nb - 1) {
            *cnt = 0;
            __threadfence();
            atomicAdd(gen, 1);
        } else {
            while (*((volatile unsigned*)gen) == my) { __nanosleep(64); }
            __threadfence();
        }
    }
    __syncthreads();
}

// ---------------- kernel: CSR build (persistent, dedicated barrier) ----------------
__global__ __launch_bounds__(256) void k_csr(const int* __restrict__ ei, int E, int ET,
                                             int n, int nb) {
    __shared__ int sh[256];
    int tid = threadIdx.x, bid = blockIdx.x;
    int gsz = nb * 256, gtid = bid * 256 + tid;

    for (int i = gtid; i < SCAN_N; i += gsz) g_deg[i] = 0;
    grid_sync_slot(&g_ccount, &g_cgen, nb);

    for (int i = gtid; i < ET; i += gsz) {
        int d = (i < E) ? ei[E + i] : (i - E);
        atomicAdd(&g_deg[d], 1);
    }
    grid_sync_slot(&g_ccount, &g_cgen, nb);

    for (int b = bid; b < NBLK; b += nb) {
        sh[tid] = g_deg[b * 256 + tid];
        __syncthreads();
        for (int o = 128; o > 0; o >>= 1) {
            if (tid < o) sh[tid] += sh[tid + o];
            __syncthreads();
        }
        if (tid == 0) g_bsum[b] = sh[0];
        __syncthreads();
    }
    grid_sync_slot(&g_ccount, &g_cgen, nb);

    if (bid == 0) {
        int v = (tid < NBLK) ? g_bsum[tid] : 0;
        sh[tid] = v;
        __syncthreads();
        for (int o = 1; o < 256; o <<= 1) {
            int t = (tid >= o) ? sh[tid - o] : 0;
            __syncthreads();
            sh[tid] += t;
            __syncthreads();
        }
        if (tid < NBLK) g_bsum[tid] = sh[tid] - v;
    }
    grid_sync_slot(&g_ccount, &g_cgen, nb);

    for (int b = bid; b < NBLK; b += nb) {
        int gi = b * 256 + tid;
        int v = g_deg[gi];
        sh[tid] = v;
        __syncthreads();
        for (int o = 1; o < 256; o <<= 1) {
            int t = (tid >= o) ? sh[tid - o] : 0;
            __syncthreads();
            sh[tid] += t;
            __syncthreads();
        }
        int ex = sh[tid] - v + g_bsum[b];
        if (gi <= n) g_off[gi] = ex;
        if (gi < n)  g_cursor[gi] = ex;
        __syncthreads();
    }
    grid_sync_slot(&g_ccount, &g_cgen, nb);

    for (int i = gtid; i < ET; i += gsz) {
        int s, d;
        if (i < E) { s = ei[i]; d = ei[E + i]; }
        else       { s = d = i - E; }
        g_csr[atomicAdd(&g_cursor[d], 1)] = s;
    }
}

// ---------------- BN stats: 1024-thr blocks, 148 arrivals, float4 streaming --------
// Channel invariant: stride nb*1024 float4s ≡ 0 mod 32, so thread tid's channel
// group is fixed: 4*(tid & 31) .. +3.
__global__ __launch_bounds__(1024) void k_bnr(const float* __restrict__ A, int total,
                                              const float* __restrict__ bg,
                                              const float* __restrict__ bb,
                                              float inv_n, int nb) {
    const float4* H4 = (const float4*)(A ? A : g_H);
    __shared__ float4 ss[1024], qq[1024];
    int tid = threadIdx.x, bid = blockIdx.x;
    int total4 = total >> 2;
    float4 s = {0.f, 0.f, 0.f, 0.f}, q = {0.f, 0.f, 0.f, 0.f};
    for (int e = bid * 1024 + tid; e < total4; e += nb * 1024) {
        float4 v = H4[e];
        s.x += v.x; s.y += v.y; s.z += v.z; s.w += v.w;
        q.x += v.x * v.x; q.y += v.y * v.y; q.z += v.z * v.z; q.w += v.w * v.w;
    }
    ss[tid] = s; qq[tid] = q;
    __syncthreads();
    if (tid < 32) {
        float4 S = ss[tid], Q = qq[tid];
        for (int t = tid + 32; t < 1024; t += 32) {
            float4 a = ss[t], b = qq[t];
            S.x += a.x; S.y += a.y; S.z += a.z; S.w += a.w;
            Q.x += b.x; Q.y += b.y; Q.z += b.z; Q.w += b.w;
        }
        int c = tid * 4;
        g_red[bid * 256 + c]     = S.x;
        g_red[bid * 256 + c + 1] = S.y;
        g_red[bid * 256 + c + 2] = S.z;
        g_red[bid * 256 + c + 3] = S.w;
        g_red[bid * 256 + 128 + c]     = Q.x;
        g_red[bid * 256 + 128 + c + 1] = Q.y;
        g_red[bid * 256 + 128 + c + 2] = Q.z;
        g_red[bid * 256 + 128 + c + 3] = Q.w;
    }
    grid_sync_slot(&g_bcount, &g_bgen, nb);
    if (bid == 0 && tid < 128) {
        float s2 = 0.f, q2 = 0.f;
        for (int b = 0; b < nb; b++) {
            s2 += g_red[b * 256 + tid];
            q2 += g_red[b * 256 + 128 + tid];
        }
        float mu  = s2 * inv_n;
        float var = q2 * inv_n - mu * mu;
        float sc  = bg[tid] * rsqrtf(var + BN_EPS);
        g_scale[tid] = sc;
        g_shift[tid] = bb[tid] - mu * sc;
    }
}

// ---------------- weight prep (side stream, data-independent) ----------------
__global__ void k_prep12(int l, const float* __restrict__ W, const float* __restrict__ lw,
                         const float* __restrict__ lb, const float* __restrict__ as,
                         const float* __restrict__ ad) {
    int idx = blockIdx.x * 256 + threadIdx.x;
    if (idx >= 128 * 260) return;
    int k = idx / 260, j = idx % 260;
    float v;
    if (j < 128)       v = W[k * 128 + j];
    else if (j < 256)  v = lw[k * 128 + (j - 128)];
    else {
        int t = j - 256;
        int hh = t & 1;
        const float* a = (t < 2) ? as : ad;
        float s = 0.f;
        for (int f = 0; f < 64; f++) s += W[k * 128 + hh * 64 + f] * a[hh * 64 + f];
        v = s;
    }
    if (j < 256) {
        __nv_bfloat16 h = __float2bfloat16(v);
        g_Bhi[l][j * 128 + k] = h;
        g_Blo[l][j * 128 + k] = __float2bfloat16(v - __bfloat162float(h));
        if (k == 0) g_bcatL[l][j] = (j >= 128) ? lb[j - 128] : 0.f;
    } else {
        g_wesd[l][k * 4 + (j - 256)] = v;
    }
}

// ---------------- mma helpers ----------------
__device__ __forceinline__ uint32_t smem_u32(const void* p) {
    uint32_t a;
    asm("{ .reg .u64 t; cvta.to.shared.u64 t, %1; cvt.u32.u64 %0, t; }" : "=r"(a) : "l"(p));
    return a;
}
__device__ __forceinline__ void ldsm_x4(uint32_t* r, uint32_t addr) {
    asm volatile("ldmatrix.sync.aligned.m8n8.x4.shared.b16 {%0,%1,%2,%3}, [%4];"
        : "=r"(r[0]), "=r"(r[1]), "=r"(r[2]), "=r"(r[3]) : "r"(addr));
}
__device__ __forceinline__ void ldsm_x2(uint32_t* r, uint32_t addr) {
    asm volatile("ldmatrix.sync.aligned.m8n8.x2.shared.b16 {%0,%1}, [%2];"
        : "=r"(r[0]), "=r"(r[1]) : "r"(addr));
}
__device__ __forceinline__ void mma_bf16(float* d, const uint32_t* a, const uint32_t* b) {
    asm volatile("mma.sync.aligned.m16n8k16.row.col.f32.bf16.bf16.f32 "
        "{%0,%1,%2,%3}, {%4,%5,%6,%7}, {%8,%9}, {%0,%1,%2,%3};"
        : "+f"(d[0]), "+f"(d[1]), "+f"(d[2]), "+f"(d[3])
        : "r"(a[0]), "r"(a[1]), "r"(a[2]), "r"(a[3]), "r"(b[0]), "r"(b[1]));
}
__device__ __forceinline__ float leaky(float x) { return (x > 0.f) ? x : LEAKY * x; }

// ---------------- tensor-core GEMM + fused esd ----------------
#define APAD 136
#define TILE_BYTES (128 * APAD * 2)
#define GEMM_SMEM  (4 * TILE_BYTES + 2048)

__global__ __launch_bounds__(256, 1) void k_gemm_mma(int l, const float* __restrict__ Ain, int M) {
    const float* A = Ain ? Ain : g_H;
    extern __shared__ char sm[];
    __nv_bfloat16* sAhi = (__nv_bfloat16*)sm;
    __nv_bfloat16* sAlo = (__nv_bfloat16*)(sm + TILE_BYTES);
    __nv_bfloat16* sBhi = (__nv_bfloat16*)(sm + 2 * TILE_BYTES);
    __nv_bfloat16* sBlo = (__nv_bfloat16*)(sm + 3 * TILE_BYTES);
    float* wesd = (float*)(sm + 4 * TILE_BYTES);

    int tid = threadIdx.x, lane = tid & 31, wid = tid >> 5;
    int warp_m = wid & 1;
    int warp_n = wid >> 1;
    int m0 = blockIdx.x * 128;
    int n0 = blockIdx.y * 128;

    for (int idx = tid; idx < 4096; idx += 256) {
        int row = idx >> 5, c = (idx & 31) * 4;
        int gm = m0 + row;
        float4 t = (gm < M) ? *(const float4*)(A + gm * 128 + c)
                            : make_float4(0.f, 0.f, 0.f, 0.f);
        float v0 = t.x * g_scale[c]     + g_shift[c];
        float v1 = t.y * g_scale[c + 1] + g_shift[c + 1];
        float v2 = t.z * g_scale[c + 2] + g_shift[c + 2];
        float v3 = t.w * g_scale[c + 3] + g_shift[c + 3];
        if (gm >= M) { v0 = v1 = v2 = v3 = 0.f; }
        __nv_bfloat16 h0 = __float2bfloat16(v0), h1 = __float2bfloat16(v1);
        __nv_bfloat16 h2 = __float2bfloat16(v2), h3 = __float2bfloat16(v3);
        __nv_bfloat162 hp0(h0, h1), hp1(h2, h3);
        __nv_bfloat162 lp0(__float2bfloat16(v0 - __bfloat162float(h0)),
                           __float2bfloat16(v1 - __bfloat162float(h1)));
        __nv_bfloat162 lp1(__float2bfloat16(v2 - __bfloat162float(h2)),
                           __float2bfloat16(v3 - __bfloat162float(h3)));
        int o = row * APAD + c;
        *(__nv_bfloat162*)(sAhi + o)     = hp0;
        *(__nv_bfloat162*)(sAhi + o + 2) = hp1;
        *(__nv_bfloat162*)(sAlo + o)     = lp0;
        *(__nv_bfloat162*)(sAlo + o + 2) = lp1;
    }
    for (int idx = tid; idx < 2048; idx += 256) {
        int row = idx >> 4, c = (idx & 15) * 8;
        int gn = n0 + row;
        uint4 hv = *(const uint4*)(g_Bhi[l] + gn * 128 + c);
        uint4 lv = *(const uint4*)(g_Blo[l] + gn * 128 + c);
        int o = row * APAD + c;
        *(uint4*)(sBhi + o) = hv;
        *(uint4*)(sBlo + o) = lv;
    }
    if (blockIdx.y == 1)
        for (int i = tid; i < 512; i += 256) wesd[i] = g_wesd[l][i];
    __syncthreads();

    int rA = lane & 15, cA = (lane >> 4) * 8;
    int rB = lane & 7,  cB = ((lane >> 3) & 1) * 8;
    uint32_t baseAhi[4], baseAlo[4], baseBhi[4], baseBlo[4];
#pragma unroll
    for (int mt = 0; mt < 4; mt++) {
        int row = warp_m * 64 + mt * 16 + rA;
        baseAhi[mt] = smem_u32(sAhi + row * APAD + cA);
        baseAlo[mt] = smem_u32(sAlo + row * APAD + cA);
    }
#pragma unroll
    for (int nt = 0; nt < 4; nt++) {
        int row = warp_n * 32 + nt * 8 + rB;
        baseBhi[nt] = smem_u32(sBhi + row * APAD + cB);
        baseBlo[nt] = smem_u32(sBlo + row * APAD + cB);
    }

    float acc[4][4][4] = {};
#pragma unroll
    for (int ks = 0; ks < 8; ks++) {
        uint32_t koff = ks * 32;
        uint32_t ahi[4][4], alo[4][4], bhi[4][2], blo[4][2];
#pragma unroll
        for (int mt = 0; mt < 4; mt++) {
            ldsm_x4(ahi[mt], baseAhi[mt] + koff);
            ldsm_x4(alo[mt], baseAlo[mt] + koff);
        }
#pragma unroll
        for (int nt = 0; nt < 4; nt++) {
            ldsm_x2(bhi[nt], baseBhi[nt] + koff);
            ldsm_x2(blo[nt], baseBlo[nt] + koff);
        }
#pragma unroll
        for (int mt = 0; mt < 4; mt++)
#pragma unroll
            for (int nt = 0; nt < 4; nt++) {
                mma_bf16(acc[mt][nt], ahi[mt], bhi[nt]);
                mma_bf16(acc[mt][nt], ahi[mt], blo[nt]);
                mma_bf16(acc[mt][nt], alo[mt], bhi[nt]);
            }
    }

    // ---- epilogue ----
#pragma unroll
    for (int mt = 0; mt < 4; mt++) {
        int gm0 = m0 + warp_m * 64 + mt * 16 + (lane >> 2);
#pragma unroll
        for (int nt = 0; nt < 4; nt++) {
            int col = warp_n * 32 + nt * 8 + (lane & 3) * 2;
            float b0 = g_bcatL[l][n0 + col], b1 = g_bcatL[l][n0 + col + 1];
            if (blockIdx.y == 0) {
                if (gm0 < M)
                    *(__half2*)(g_HWh + gm0 * 128 + col) =
                        __floats2half2_rn(acc[mt][nt][0] + b0, acc[mt][nt][1] + b1);
                if (gm0 + 8 < M)
                    *(__half2*)(g_HWh + (gm0 + 8) * 128 + col) =
                        __floats2half2_rn(acc[mt][nt][2] + b0, acc[mt][nt][3] + b1);
            } else {
                if (gm0 < M) {
                    float2 v = {acc[mt][nt][0] + b0, acc[mt][nt][1] + b1};
                    *(float2*)(g_HL + gm0 * 128 + col) = v;
                }
                if (gm0 + 8 < M) {
                    float2 v = {acc[mt][nt][2] + b0, acc[mt][nt][3] + b1};
                    *(float2*)(g_HL + (gm0 + 8) * 128 + col) = v;
                }
            }
        }
    }

    if (blockIdx.y == 1) {
        for (int r = 0; r < 16; r++) {
            int row = wid * 16 + r;
            int gm = m0 + row;
            int k = lane * 4;
            int o = row * APAD + k;
            float a0 = __bfloat162float(sAhi[o])     + __bfloat162float(sAlo[o]);
            float a1 = __bfloat162float(sAhi[o + 1]) + __bfloat162float(sAlo[o + 1]);
            float a2 = __bfloat162float(sAhi[o + 2]) + __bfloat162float(sAlo[o + 2]);
            float a3 = __bfloat162float(sAhi[o + 3]) + __bfloat162float(sAlo[o + 3]);
            float s0 = a0 * wesd[k * 4]     + a1 * wesd[(k + 1) * 4]     + a2 * wesd[(k + 2) * 4]     + a3 * wesd[(k + 3) * 4];
            float s1 = a0 * wesd[k * 4 + 1] + a1 * wesd[(k + 1) * 4 + 1] + a2 * wesd[(k + 2) * 4 + 1] + a3 * wesd[(k + 3) * 4 + 1];
            float s2 = a0 * wesd[k * 4 + 2] + a1 * wesd[(k + 1) * 4 + 2] + a2 * wesd[(k + 2) * 4 + 2] + a3 * wesd[(k + 3) * 4 + 2];
            float s3 = a0 * wesd[k * 4 + 3] + a1 * wesd[(k + 1) * 4 + 3] + a2 * wesd[(k + 2) * 4 + 3] + a3 * wesd[(k + 3) * 4 + 3];
#pragma unroll
            for (int sh = 16; sh > 0; sh >>= 1) {
                s0 += __shfl_xor_sync(0xffffffffu, s0, sh);
                s1 += __shfl_xor_sync(0xffffffffu, s1, sh);
                s2 += __shfl_xor_sync(0xffffffffu, s2, sh);
                s3 += __shfl_xor_sync(0xffffffffu, s3, sh);
            }
            if (lane == 0 && gm < M) {
                g_ESDs[gm] = make_float2(s0, s1);
                g_ESDd[gm] = make_float2(s2, s3);
            }
        }
    }
}

// ---------------- layer 3 GEMV (self-prep weights) ----------------
__global__ __launch_bounds__(256) void k_gemv6(const float* __restrict__ W3,
                                               const float* __restrict__ lw3,
                                               const float* __restrict__ lb3,
                                               const float* __restrict__ as3,
                                               const float* __restrict__ ad3,
                                               int n) {
    const float* A = g_H;
    __shared__ float ws[768];
    __shared__ float bs[8];
    int tid = threadIdx.x;
    for (int i = tid; i < 768; i += 256) {
        int k = i / 6, j = i % 6;
        float v;
        if (j < 2)      v = W3[k * 2 + j];
        else if (j < 4) v = lw3[k * 2 + (j - 2)];
        else {
            const float* a = (j == 4) ? as3 : ad3;
            v = W3[k * 2] * a[0] + W3[k * 2 + 1] * a[1];
        }
        ws[i] = v;
    }
    if (tid < 2) bs[tid] = lb3[tid];
    __syncthreads();
    int row = blockIdx.x * 8 + (tid >> 5);
    int lane = tid & 31;
    if (row >= n) return;
    float4 a = ((const float4*)A)[row * 32 + lane];
    int k = lane * 4;
    float a0 = a.x * g_scale[k]     + g_shift[k];
    float a1 = a.y * g_scale[k + 1] + g_shift[k + 1];
    float a2 = a.z * g_scale[k + 2] + g_shift[k + 2];
    float a3 = a.w * g_scale[k + 3] + g_shift[k + 3];
    float c[6];
#pragma unroll
    for (int j = 0; j < 6; j++)
        c[j] = a0 * ws[k * 6 + j] + a1 * ws[(k + 1) * 6 + j] +
               a2 * ws[(k + 2) * 6 + j] + a3 * ws[(k + 3) * 6 + j];
#pragma unroll
    for (int j = 0; j < 6; j++)
#pragma unroll
        for (int o = 16; o > 0; o >>= 1) c[j] += __shfl_xor_sync(0xffffffffu, c[j], o);
    if (lane == 0) {
        g_HW[row * 2]     = c[0];
        g_HW[row * 2 + 1] = c[1];
        g_HL[row * 2]     = c[2] + bs[0];
        g_HL[row * 2 + 1] = c[3] + bs[1];
        g_ESDs[row] = make_float2(c[4], 0.f);
        g_ESDd[row] = make_float2(c[5], 0.f);
    }
}

// ---------------- GAT edge phase, layers 1/2 (single-pass, fp16 gather) ----------------
__global__ __launch_bounds__(256) void k_gat_edge12(const float* __restrict__ gb, int n) {
    int warp = (blockIdx.x * 256 + threadIdx.x) >> 5;
    int lane = threadIdx.x & 31;
    if (warp >= n) return;
    int node = warp;
    int beg = g_off[node], end = g_off[node + 1];
    float2 ed = g_ESDd[node];
    const uint2* HWh2 = (const uint2*)g_HWh;

    float sum0 = 0.f, sum1 = 0.f;
    float ax = 0.f, ay = 0.f, az = 0.f, aw = 0.f;
    for (int base = beg; base < end; base += 32) {
        int i = base + lane;
        int s = 0;
        float p0 = 0.f, p1 = 0.f;
        if (i < end) {
            s = g_csr[i];
            float2 e = g_ESDs[s];
            p0 = __expf(leaky(e.x + ed.x));
            p1 = __expf(leaky(e.y + ed.y));
        }
        sum0 += p0; sum1 += p1;
        int cnt = min(32, end - base);
        if (cnt == 32) {
#pragma unroll
            for (int j = 0; j < 32; j++) {
                int sj   = __shfl_sync(0xffffffffu, s, j);
                float q0 = __shfl_sync(0xffffffffu, p0, j);
                float q1 = __shfl_sync(0xffffffffu, p1, j);
                float ph = (lane < 16) ? q0 : q1;
                uint2 hv = HWh2[sj * 32 + lane];
                float2 f01 = __half22float2(*(__half2*)&hv.x);
                float2 f23 = __half22float2(*(__half2*)&hv.y);
                ax += ph * f01.x; ay += ph * f01.y; az += ph * f23.x; aw += ph * f23.y;
            }
        } else {
            for (int j = 0; j < cnt; j++) {
                int sj   = __shfl_sync(0xffffffffu, s, j);
                float q0 = __shfl_sync(0xffffffffu, p0, j);
                float q1 = __shfl_sync(0xffffffffu, p1, j);
                float ph = (lane < 16) ? q0 : q1;
                uint2 hv = HWh2[sj * 32 + lane];
                float2 f01 = __half22float2(*(__half2*)&hv.x);
                float2 f23 = __half22float2(*(__half2*)&hv.y);
                ax += ph * f01.x; ay += ph * f01.y; az += ph * f23.x; aw += ph * f23.y;
            }
        }
    }
#pragma unroll
    for (int o = 16; o > 0; o >>= 1) {
        sum0 += __shfl_xor_sync(0xffffffffu, sum0, o);
        sum1 += __shfl_xor_sync(0xffffffffu, sum1, o);
    }
    float inv = 1.f / ((lane < 16) ? sum0 : sum1);

    float4 hl = ((const float4*)g_HL)[node * 32 + lane];
    float4 gv = ((const float4*)gb)[lane];
    float4 o4;
    o4.x = fmaxf(hl.x + gv.x + ax * inv, 0.f);
    o4.y = fmaxf(hl.y + gv.y + ay * inv, 0.f);
    o4.z = fmaxf(hl.z + gv.z + az * inv, 0.f);
    o4.w = fmaxf(hl.w + gv.w + aw * inv, 0.f);
    ((float4*)g_H)[node * 32 + lane] = o4;
}

// ---------------- GAT edge phase, layer 3 (single-pass) ----------------
__global__ __launch_bounds__(256) void k_gat_edge3(const float* __restrict__ gb3,
                                                   float* __restrict__ out, int n) {
    int warp = (blockIdx.x * 256 + threadIdx.x) >> 5;
    int lane = threadIdx.x & 31;
    if (warp >= n) return;
    int node = warp;
    int beg = g_off[node], end = g_off[node + 1];
    float edv = g_ESDd[node].x;
    const float2* HW2 = (const float2*)g_HW;

    float sum = 0.f, a0 = 0.f, a1 = 0.f;
    for (int i = beg + lane; i < end; i += 32) {
        int s = g_csr[i];
        float p = __expf(leaky(g_ESDs[s].x + edv));
        float2 h = HW2[s];
        sum += p;
        a0 += p * h.x;
        a1 += p * h.y;
    }
#pragma unroll
    for (int o = 16; o > 0; o >>= 1) {
        sum += __shfl_xor_sync(0xffffffffu, sum, o);
        a0  += __shfl_xor_sync(0xffffffffu, a0, o);
        a1  += __shfl_xor_sync(0xffffffffu, a1, o);
    }
    if (lane == 0) {
        float inv = 1.f / sum;
        out[node * 2]     = fmaxf(g_HL[node * 2]     + gb3[0] + a0 * inv, 0.f);
        out[node * 2 + 1] = fmaxf(g_HL[node * 2 + 1] + gb3[1] + a1 * inv, 0.f);
    }
}

// ---------------- host launch ----------------
extern "C" void kernel_launch(void* const* d_in, const int* in_sizes, int n_in,
                              void* d_out, int out_size) {
    const float* x  = (const float*)d_in[0];
    const int*   ei = (const int*)d_in[1];
    const float *W1 = (const float*)d_in[2],  *as1 = (const float*)d_in[3],
                *ad1 = (const float*)d_in[4], *gb1 = (const float*)d_in[5],
                *lw1 = (const float*)d_in[6], *lb1 = (const float*)d_in[7],
                *bg1 = (const float*)d_in[8], *bb1 = (const float*)d_in[9];
    const float *W2 = (const float*)d_in[10], *as2 = (const float*)d_in[11],
                *ad2 = (const float*)d_in[12], *gb2 = (const float*)d_in[13],
                *lw2 = (const float*)d_in[14], *lb2 = (const float*)d_in[15],
                *bg2 = (const float*)d_in[16], *bb2 = (const float*)d_in[17];
    const float *W3 = (const float*)d_in[18], *as3 = (const float*)d_in[19],
                *ad3 = (const float*)d_in[20], *gb3 = (const float*)d_in[21],
                *lw3 = (const float*)d_in[22], *lb3 = (const float*)d_in[23],
                *bg3 = (const float*)d_in[24], *bb3 = (const float*)d_in[25];
    (void)n_in; (void)out_size;

    int n  = in_sizes[0] / 128;
    int E  = in_sizes[1] / 2;
    int ET = E + n;
    float* out = (float*)d_out;
    float inv_n = 1.f / (float)n;

    dim3 gg((n + 127) / 128, 2);
    int wb = (n + 7) / 8;

    static int inited = 0;
    static cudaStream_t s1 = nullptr, s2 = nullptr;
    static cudaEvent_t ev_fork = nullptr, ev_p1 = nullptr, ev_p2 = nullptr,
                       ev_csr = nullptr, ev_b1 = nullptr;
    if (!inited) {
        cudaFuncSetAttribute(k_gemm_mma, cudaFuncAttributeMaxDynamicSharedMemorySize, GEMM_SMEM);
        cudaStreamCreateWithFlags(&s1, cudaStreamNonBlocking);
        cudaStreamCreateWithFlags(&s2, cudaStreamNonBlocking);
        cudaEventCreateWithFlags(&ev_fork, cudaEventDisableTiming);
        cudaEventCreateWithFlags(&ev_p1, cudaEventDisableTiming);
        cudaEventCreateWithFlags(&ev_p2, cudaEventDisableTiming);
        cudaEventCreateWithFlags(&ev_csr, cudaEventDisableTiming);
        cudaEventCreateWithFlags(&ev_b1, cudaEventDisableTiming);
        inited = 1;
    }

    // ---- fork side work ----
    cudaEventRecord(ev_fork, 0);
    cudaStreamWaitEvent(s1, ev_fork, 0);
    cudaStreamWaitEvent(s2, ev_fork, 0);

    // s1: weight preps (data-independent)
    k_prep12<<<131, 256, 0, s1>>>(0, W1, lw1, lb1, as1, ad1);
    cudaEventRecord(ev_p1, s1);
    k_prep12<<<131, 256, 0, s1>>>(1, W2, lw2, lb2, as2, ad2);
    cudaEventRecord(ev_p2, s1);

    // s2: layer-1 BN stats (reads only x), then CSR build
    k_bnr<<<NSM, 1024, 0, s2>>>(x, n * 128, bg1, bb1, inv_n, NSM);
    cudaEventRecord(ev_b1, s2);
    k_csr<<<NSM, 256, 0, s2>>>(ei, E, ET, n, NSM);
    cudaEventRecord(ev_csr, s2);

    // ---- main chain (8 nodes) ----
    cudaStreamWaitEvent(0, ev_p1, 0);
    cudaStreamWaitEvent(0, ev_b1, 0);
    k_gemm_mma<<<gg, 256, GEMM_SMEM>>>(0, x, n);
    cudaStreamWaitEvent(0, ev_csr, 0);
    k_gat_edge12<<<wb, 256>>>(gb1, n);

    k_bnr<<<NSM, 1024>>>(nullptr, n * 128, bg2, bb2, inv_n, NSM);
    cudaStreamWaitEvent(0, ev_p2, 0);
    k_gemm_mma<<<gg, 256, GEMM_SMEM>>>(1, nullptr, n);
    k_gat_edge12<<<wb, 256>>>(gb2, n);

    k_bnr<<<NSM, 1024>>>(nullptr, n * 128, bg3, bb3, inv_n, NSM);
    k_gemv6<<<wb, 256>>>(W3, lw3, lb3, as3, ad3, n);
    k_gat_edge3<<<wb, 256>>>(gb3, out, n);
}

// round 14
// speedup vs baseline: 1.1027x; 1.1024x over previous
#include <cuda_runtime.h>
#include <cuda_bf16.h>
#include <cuda_fp16.h>
#include <cstdint>

#define LEAKY 0.2f
#define BN_EPS 1e-5f
#define MAXN 50000
#define MAXE 1600000
#define MAXET (MAXN + MAXE)
#define SCAN_N 50176
#define NBLK 196
#define NSM 148

// ---------------- device scratch ----------------
__device__ int   g_deg[SCAN_N];
__device__ int   g_off[MAXN + 1];
__device__ int   g_cursor[MAXN];
__device__ int   g_csr[MAXET];
__device__ int   g_bsum[256];
__device__ float g_red[NSM * 256];
__device__ float g_scale[128];
__device__ float g_shift[128];
__device__ float g_HW[MAXN * 2];        // layer-3 head features (fp32)
__device__ __half g_HWh[MAXN * 128];    // layer-1/2 head features (fp16 gather payload)
__device__ float g_HL[MAXN * 128];
__device__ float2 g_ESDs[MAXN];         // per-src attention terms (es0, es1)
__device__ float2 g_ESDd[MAXN];         // per-dst attention terms (ed0, ed1)
__device__ float g_H[MAXN * 128];
// double-buffered per-layer weights
__device__ __nv_bfloat16 g_Bhi[2][256 * 128];   // [n][k]
__device__ __nv_bfloat16 g_Blo[2][256 * 128];
__device__ float g_bcatL[2][256];
__device__ float g_wesd[2][512];                // [k][4]

// ---------------- software grid barriers (separate slots: bnr vs scan) -------------
__device__ unsigned g_bcount = 0, g_bgen = 0;      // k_bnr
__device__ unsigned g_ccount = 0, g_cgen = 0;      // k_scan

__device__ __forceinline__ void grid_sync_slot(unsigned* cnt, unsigned* gen, int nb) {
    __syncthreads();
    if (threadIdx.x == 0) {
        unsigned my = *((volatile unsigned*)gen);
        __threadfence();
        unsigned old = atomicAdd(cnt, 1);
        if (old == (unsigned)nb - 1) {
            *cnt = 0;
            __threadfence();
            atomicAdd(gen, 1);
        } else {
            while (*((volatile unsigned*)gen) == my) { __nanosleep(64); }
            __threadfence();
        }
    }
    __syncthreads();
}

// ---------------- CSR build: wide-grid count/scatter + persistent scan -------------
__global__ void k_zero_deg() {
    int i = blockIdx.x * 256 + threadIdx.x;
    if (i < SCAN_N) g_deg[i] = 0;
}
__global__ void k_count(const int* __restrict__ ei, int E, int ET) {
    int i = blockIdx.x * 256 + threadIdx.x;
    if (i < ET) {
        int d = (i < E) ? ei[E + i] : (i - E);
        atomicAdd(&g_deg[d], 1);
    }
}
__global__ __launch_bounds__(256) void k_scan(int n, int nb) {
    __shared__ int sh[256];
    int tid = threadIdx.x, bid = blockIdx.x;

    for (int b = bid; b < NBLK; b += nb) {
        sh[tid] = g_deg[b * 256 + tid];
        __syncthreads();
        for (int o = 128; o > 0; o >>= 1) {
            if (tid < o) sh[tid] += sh[tid + o];
            __syncthreads();
        }
        if (tid == 0) g_bsum[b] = sh[0];
        __syncthreads();
    }
    grid_sync_slot(&g_ccount, &g_cgen, nb);

    if (bid == 0) {
        int v = (tid < NBLK) ? g_bsum[tid] : 0;
        sh[tid] = v;
        __syncthreads();
        for (int o = 1; o < 256; o <<= 1) {
            int t = (tid >= o) ? sh[tid - o] : 0;
            __syncthreads();
            sh[tid] += t;
            __syncthreads();
        }
        if (tid < NBLK) g_bsum[tid] = sh[tid] - v;
    }
    grid_sync_slot(&g_ccount, &g_cgen, nb);

    for (int b = bid; b < NBLK; b += nb) {
        int gi = b * 256 + tid;
        int v = g_deg[gi];
        sh[tid] = v;
        __syncthreads();
        for (int o = 1; o < 256; o <<= 1) {
            int t = (tid >= o) ? sh[tid - o] : 0;
            __syncthreads();
            sh[tid] += t;
            __syncthreads();
        }
        int ex = sh[tid] - v + g_bsum[b];
        if (gi <= n) g_off[gi] = ex;
        if (gi < n)  g_cursor[gi] = ex;
        __syncthreads();
    }
}
__global__ void k_scatter(const int* __restrict__ ei, int E, int ET) {
    int i = blockIdx.x * 256 + threadIdx.x;
    if (i < ET) {
        int s, d;
        if (i < E) { s = ei[i]; d = ei[E + i]; }
        else       { s = d = i - E; }
        g_csr[atomicAdd(&g_cursor[d], 1)] = s;
    }
}

// ---------------- BN stats: 1024-thr blocks, 148 arrivals, float4 streaming --------
// Channel invariant: stride nb*1024 float4s ≡ 0 mod 32, so thread tid's channel
// group is fixed: 4*(tid & 31) .. +3.
__global__ __launch_bounds__(1024) void k_bnr(const float* __restrict__ A, int total,
                                              const float* __restrict__ bg,
                                              const float* __restrict__ bb,
                                              float inv_n, int nb) {
    const float4* H4 = (const float4*)(A ? A : g_H);
    __shared__ float4 ss[1024], qq[1024];
    int tid = threadIdx.x, bid = blockIdx.x;
    int total4 = total >> 2;
    float4 s = {0.f, 0.f, 0.f, 0.f}, q = {0.f, 0.f, 0.f, 0.f};
    for (int e = bid * 1024 + tid; e < total4; e += nb * 1024) {
        float4 v = H4[e];
        s.x += v.x; s.y += v.y; s.z += v.z; s.w += v.w;
        q.x += v.x * v.x; q.y += v.y * v.y; q.z += v.z * v.z; q.w += v.w * v.w;
    }
    ss[tid] = s; qq[tid] = q;
    __syncthreads();
    if (tid < 32) {
        float4 S = ss[tid], Q = qq[tid];
        for (int t = tid + 32; t < 1024; t += 32) {
            float4 a = ss[t], b = qq[t];
            S.x += a.x; S.y += a.y; S.z += a.z; S.w += a.w;
            Q.x += b.x; Q.y += b.y; Q.z += b.z; Q.w += b.w;
        }
        int c = tid * 4;
        g_red[bid * 256 + c]     = S.x;
        g_red[bid * 256 + c + 1] = S.y;
        g_red[bid * 256 + c + 2] = S.z;
        g_red[bid * 256 + c + 3] = S.w;
        g_red[bid * 256 + 128 + c]     = Q.x;
        g_red[bid * 256 + 128 + c + 1] = Q.y;
        g_red[bid * 256 + 128 + c + 2] = Q.z;
        g_red[bid * 256 + 128 + c + 3] = Q.w;
    }
    grid_sync_slot(&g_bcount, &g_bgen, nb);
    if (bid == 0 && tid < 128) {
        float s2 = 0.f, q2 = 0.f;
        for (int b = 0; b < nb; b++) {
            s2 += g_red[b * 256 + tid];
            q2 += g_red[b * 256 + 128 + tid];
        }
        float mu  = s2 * inv_n;
        float var = q2 * inv_n - mu * mu;
        float sc  = bg[tid] * rsqrtf(var + BN_EPS);
        g_scale[tid] = sc;
        g_shift[tid] = bb[tid] - mu * sc;
    }
}

// ---------------- weight prep (side stream, data-independent) ----------------
__global__ void k_prep12(int l, const float* __restrict__ W, const float* __restrict__ lw,
                         const float* __restrict__ lb, const float* __restrict__ as,
                         const float* __restrict__ ad) {
    int idx = blockIdx.x * 256 + threadIdx.x;
    if (idx >= 128 * 260) return;
    int k = idx / 260, j = idx % 260;
    float v;
    if (j < 128)       v = W[k * 128 + j];
    else if (j < 256)  v = lw[k * 128 + (j - 128)];
    else {
        int t = j - 256;
        int hh = t & 1;
        const float* a = (t < 2) ? as : ad;
        float s = 0.f;
        for (int f = 0; f < 64; f++) s += W[k * 128 + hh * 64 + f] * a[hh * 64 + f];
        v = s;
    }
    if (j < 256) {
        __nv_bfloat16 h = __float2bfloat16(v);
        g_Bhi[l][j * 128 + k] = h;
        g_Blo[l][j * 128 + k] = __float2bfloat16(v - __bfloat162float(h));
        if (k == 0) g_bcatL[l][j] = (j >= 128) ? lb[j - 128] : 0.f;
    } else {
        g_wesd[l][k * 4 + (j - 256)] = v;
    }
}

// ---------------- mma helpers ----------------
__device__ __forceinline__ uint32_t smem_u32(const void* p) {
    uint32_t a;
    asm("{ .reg .u64 t; cvta.to.shared.u64 t, %1; cvt.u32.u64 %0, t; }" : "=r"(a) : "l"(p));
    return a;
}
__device__ __forceinline__ void ldsm_x4(uint32_t* r, uint32_t addr) {
    asm volatile("ldmatrix.sync.aligned.m8n8.x4.shared.b16 {%0,%1,%2,%3}, [%4];"
        : "=r"(r[0]), "=r"(r[1]), "=r"(r[2]), "=r"(r[3]) : "r"(addr));
}
__device__ __forceinline__ void ldsm_x2(uint32_t* r, uint32_t addr) {
    asm volatile("ldmatrix.sync.aligned.m8n8.x2.shared.b16 {%0,%1}, [%2];"
        : "=r"(r[0]), "=r"(r[1]) : "r"(addr));
}
__device__ __forceinline__ void mma_bf16(float* d, const uint32_t* a, const uint32_t* b) {
    asm volatile("mma.sync.aligned.m16n8k16.row.col.f32.bf16.bf16.f32 "
        "{%0,%1,%2,%3}, {%4,%5,%6,%7}, {%8,%9}, {%0,%1,%2,%3};"
        : "+f"(d[0]), "+f"(d[1]), "+f"(d[2]), "+f"(d[3])
        : "r"(a[0]), "r"(a[1]), "r"(a[2]), "r"(a[3]), "r"(b[0]), "r"(b[1]));
}
__device__ __forceinline__ float leaky(float x) { return (x > 0.f) ? x : LEAKY * x; }

// ---------------- tensor-core GEMM + fused esd ----------------
#define APAD 136
#define TILE_BYTES (128 * APAD * 2)
#define GEMM_SMEM  (4 * TILE_BYTES + 2048)

__global__ __launch_bounds__(256, 1) void k_gemm_mma(int l, const float* __restrict__ Ain, int M) {
    const float* A = Ain ? Ain : g_H;
    extern __shared__ char sm[];
    __nv_bfloat16* sAhi = (__nv_bfloat16*)sm;
    __nv_bfloat16* sAlo = (__nv_bfloat16*)(sm + TILE_BYTES);
    __nv_bfloat16* sBhi = (__nv_bfloat16*)(sm + 2 * TILE_BYTES);
    __nv_bfloat16* sBlo = (__nv_bfloat16*)(sm + 3 * TILE_BYTES);
    float* wesd = (float*)(sm + 4 * TILE_BYTES);

    int tid = threadIdx.x, lane = tid & 31, wid = tid >> 5;
    int warp_m = wid & 1;
    int warp_n = wid >> 1;
    int m0 = blockIdx.x * 128;
    int n0 = blockIdx.y * 128;

    for (int idx = tid; idx < 4096; idx += 256) {
        int row = idx >> 5, c = (idx & 31) * 4;
        int gm = m0 + row;
        float4 t = (gm < M) ? *(const float4*)(A + gm * 128 + c)
                            : make_float4(0.f, 0.f, 0.f, 0.f);
        float v0 = t.x * g_scale[c]     + g_shift[c];
        float v1 = t.y * g_scale[c + 1] + g_shift[c + 1];
        float v2 = t.z * g_scale[c + 2] + g_shift[c + 2];
        float v3 = t.w * g_scale[c + 3] + g_shift[c + 3];
        if (gm >= M) { v0 = v1 = v2 = v3 = 0.f; }
        __nv_bfloat16 h0 = __float2bfloat16(v0), h1 = __float2bfloat16(v1);
        __nv_bfloat16 h2 = __float2bfloat16(v2), h3 = __float2bfloat16(v3);
        __nv_bfloat162 hp0(h0, h1), hp1(h2, h3);
        __nv_bfloat162 lp0(__float2bfloat16(v0 - __bfloat162float(h0)),
                           __float2bfloat16(v1 - __bfloat162float(h1)));
        __nv_bfloat162 lp1(__float2bfloat16(v2 - __bfloat162float(h2)),
                           __float2bfloat16(v3 - __bfloat162float(h3)));
        int o = row * APAD + c;
        *(__nv_bfloat162*)(sAhi + o)     = hp0;
        *(__nv_bfloat162*)(sAhi + o + 2) = hp1;
        *(__nv_bfloat162*)(sAlo + o)     = lp0;
        *(__nv_bfloat162*)(sAlo + o + 2) = lp1;
    }
    for (int idx = tid; idx < 2048; idx += 256) {
        int row = idx >> 4, c = (idx & 15) * 8;
        int gn = n0 + row;
        uint4 hv = *(const uint4*)(g_Bhi[l] + gn * 128 + c);
        uint4 lv = *(const uint4*)(g_Blo[l] + gn * 128 + c);
        int o = row * APAD + c;
        *(uint4*)(sBhi + o) = hv;
        *(uint4*)(sBlo + o) = lv;
    }
    if (blockIdx.y == 1)
        for (int i = tid; i < 512; i += 256) wesd[i] = g_wesd[l][i];
    __syncthreads();

    int rA = lane & 15, cA = (lane >> 4) * 8;
    int rB = lane & 7,  cB = ((lane >> 3) & 1) * 8;
    uint32_t baseAhi[4], baseAlo[4], baseBhi[4], baseBlo[4];
#pragma unroll
    for (int mt = 0; mt < 4; mt++) {
        int row = warp_m * 64 + mt * 16 + rA;
        baseAhi[mt] = smem_u32(sAhi + row * APAD + cA);
        baseAlo[mt] = smem_u32(sAlo + row * APAD + cA);
    }
#pragma unroll
    for (int nt = 0; nt < 4; nt++) {
        int row = warp_n * 32 + nt * 8 + rB;
        baseBhi[nt] = smem_u32(sBhi + row * APAD + cB);
        baseBlo[nt] = smem_u32(sBlo + row * APAD + cB);
    }

    float acc[4][4][4] = {};
#pragma unroll
    for (int ks = 0; ks < 8; ks++) {
        uint32_t koff = ks * 32;
        uint32_t ahi[4][4], alo[4][4], bhi[4][2], blo[4][2];
#pragma unroll
        for (int mt = 0; mt < 4; mt++) {
            ldsm_x4(ahi[mt], baseAhi[mt] + koff);
            ldsm_x4(alo[mt], baseAlo[mt] + koff);
        }
#pragma unroll
        for (int nt = 0; nt < 4; nt++) {
            ldsm_x2(bhi[nt], baseBhi[nt] + koff);
            ldsm_x2(blo[nt], baseBlo[nt] + koff);
        }
#pragma unroll
        for (int mt = 0; mt < 4; mt++)
#pragma unroll
            for (int nt = 0; nt < 4; nt++) {
                mma_bf16(acc[mt][nt], ahi[mt], bhi[nt]);
                mma_bf16(acc[mt][nt], ahi[mt], blo[nt]);
                mma_bf16(acc[mt][nt], alo[mt], bhi[nt]);
            }
    }

    // ---- epilogue ----
#pragma unroll
    for (int mt = 0; mt < 4; mt++) {
        int gm0 = m0 + warp_m * 64 + mt * 16 + (lane >> 2);
#pragma unroll
        for (int nt = 0; nt < 4; nt++) {
            int col = warp_n * 32 + nt * 8 + (lane & 3) * 2;
            float b0 = g_bcatL[l][n0 + col], b1 = g_bcatL[l][n0 + col + 1];
            if (blockIdx.y == 0) {
                if (gm0 < M)
                    *(__half2*)(g_HWh + gm0 * 128 + col) =
                        __floats2half2_rn(acc[mt][nt][0] + b0, acc[mt][nt][1] + b1);
                if (gm0 + 8 < M)
                    *(__half2*)(g_HWh + (gm0 + 8) * 128 + col) =
                        __floats2half2_rn(acc[mt][nt][2] + b0, acc[mt][nt][3] + b1);
            } else {
                if (gm0 < M) {
                    float2 v = {acc[mt][nt][0] + b0, acc[mt][nt][1] + b1};
                    *(float2*)(g_HL + gm0 * 128 + col) = v;
                }
                if (gm0 + 8 < M) {
                    float2 v = {acc[mt][nt][2] + b0, acc[mt][nt][3] + b1};
                    *(float2*)(g_HL + (gm0 + 8) * 128 + col) = v;
                }
            }
        }
    }

    if (blockIdx.y == 1) {
        for (int r = 0; r < 16; r++) {
            int row = wid * 16 + r;
            int gm = m0 + row;
            int k = lane * 4;
            int o = row * APAD + k;
            float a0 = __bfloat162float(sAhi[o])     + __bfloat162float(sAlo[o]);
            float a1 = __bfloat162float(sAhi[o + 1]) + __bfloat162float(sAlo[o + 1]);
            float a2 = __bfloat162float(sAhi[o + 2]) + __bfloat162float(sAlo[o + 2]);
            float a3 = __bfloat162float(sAhi[o + 3]) + __bfloat162float(sAlo[o + 3]);
            float s0 = a0 * wesd[k * 4]     + a1 * wesd[(k + 1) * 4]     + a2 * wesd[(k + 2) * 4]     + a3 * wesd[(k + 3) * 4];
            float s1 = a0 * wesd[k * 4 + 1] + a1 * wesd[(k + 1) * 4 + 1] + a2 * wesd[(k + 2) * 4 + 1] + a3 * wesd[(k + 3) * 4 + 1];
            float s2 = a0 * wesd[k * 4 + 2] + a1 * wesd[(k + 1) * 4 + 2] + a2 * wesd[(k + 2) * 4 + 2] + a3 * wesd[(k + 3) * 4 + 2];
            float s3 = a0 * wesd[k * 4 + 3] + a1 * wesd[(k + 1) * 4 + 3] + a2 * wesd[(k + 2) * 4 + 3] + a3 * wesd[(k + 3) * 4 + 3];
#pragma unroll
            for (int sh = 16; sh > 0; sh >>= 1) {
                s0 += __shfl_xor_sync(0xffffffffu, s0, sh);
                s1 += __shfl_xor_sync(0xffffffffu, s1, sh);
                s2 += __shfl_xor_sync(0xffffffffu, s2, sh);
                s3 += __shfl_xor_sync(0xffffffffu, s3, sh);
            }
            if (lane == 0 && gm < M) {
                g_ESDs[gm] = make_float2(s0, s1);
                g_ESDd[gm] = make_float2(s2, s3);
            }
        }
    }
}

// ---------------- layer 3 GEMV (self-prep weights) ----------------
__global__ __launch_bounds__(256) void k_gemv6(const float* __restrict__ W3,
                                               const float* __restrict__ lw3,
                                               const float* __restrict__ lb3,
                                               const float* __restrict__ as3,
                                               const float* __restrict__ ad3,
                                               int n) {
    const float* A = g_H;
    __shared__ float ws[768];
    __shared__ float bs[8];
    int tid = threadIdx.x;
    for (int i = tid; i < 768; i += 256) {
        int k = i / 6, j = i % 6;
        float v;
        if (j < 2)      v = W3[k * 2 + j];
        else if (j < 4) v = lw3[k * 2 + (j - 2)];
        else {
            const float* a = (j == 4) ? as3 : ad3;
            v = W3[k * 2] * a[0] + W3[k * 2 + 1] * a[1];
        }
        ws[i] = v;
    }
    if (tid < 2) bs[tid] = lb3[tid];
    __syncthreads();
    int row = blockIdx.x * 8 + (tid >> 5);
    int lane = tid & 31;
    if (row >= n) return;
    float4 a = ((const float4*)A)[row * 32 + lane];
    int k = lane * 4;
    float a0 = a.x * g_scale[k]     + g_shift[k];
    float a1 = a.y * g_scale[k + 1] + g_shift[k + 1];
    float a2 = a.z * g_scale[k + 2] + g_shift[k + 2];
    float a3 = a.w * g_scale[k + 3] + g_shift[k + 3];
    float c[6];
#pragma unroll
    for (int j = 0; j < 6; j++)
        c[j] = a0 * ws[k * 6 + j] + a1 * ws[(k + 1) * 6 + j] +
               a2 * ws[(k + 2) * 6 + j] + a3 * ws[(k + 3) * 6 + j];
#pragma unroll
    for (int j = 0; j < 6; j++)
#pragma unroll
        for (int o = 16; o > 0; o >>= 1) c[j] += __shfl_xor_sync(0xffffffffu, c[j], o);
    if (lane == 0) {
        g_HW[row * 2]     = c[0];
        g_HW[row * 2 + 1] = c[1];
        g_HL[row * 2]     = c[2] + bs[0];
        g_HL[row * 2 + 1] = c[3] + bs[1];
        g_ESDs[row] = make_float2(c[4], 0.f);
        g_ESDd[row] = make_float2(c[5], 0.f);
    }
}

// ---------------- GAT edge phase, layers 1/2 (single-pass, fp16 gather) ----------------
__global__ __launch_bounds__(256) void k_gat_edge12(const float* __restrict__ gb, int n) {
    int warp = (blockIdx.x * 256 + threadIdx.x) >> 5;
    int lane = threadIdx.x & 31;
    if (warp >= n) return;
    int node = warp;
    int beg = g_off[node], end = g_off[node + 1];
    float2 ed = g_ESDd[node];
    const uint2* HWh2 = (const uint2*)g_HWh;

    float sum0 = 0.f, sum1 = 0.f;
    float ax = 0.f, ay = 0.f, az = 0.f, aw = 0.f;
    for (int base = beg; base < end; base += 32) {
        int i = base + lane;
        int s = 0;
        float p0 = 0.f, p1 = 0.f;
        if (i < end) {
            s = g_csr[i];
            float2 e = g_ESDs[s];
            p0 = __expf(leaky(e.x + ed.x));
            p1 = __expf(leaky(e.y + ed.y));
        }
        sum0 += p0; sum1 += p1;
        int cnt = min(32, end - base);
        if (cnt == 32) {
#pragma unroll
            for (int j = 0; j < 32; j++) {
                int sj   = __shfl_sync(0xffffffffu, s, j);
                float q0 = __shfl_sync(0xffffffffu, p0, j);
                float q1 = __shfl_sync(0xffffffffu, p1, j);
                float ph = (lane < 16) ? q0 : q1;
                uint2 hv = HWh2[sj * 32 + lane];
                float2 f01 = __half22float2(*(__half2*)&hv.x);
                float2 f23 = __half22float2(*(__half2*)&hv.y);
                ax += ph * f01.x; ay += ph * f01.y; az += ph * f23.x; aw += ph * f23.y;
            }
        } else {
            for (int j = 0; j < cnt; j++) {
                int sj   = __shfl_sync(0xffffffffu, s, j);
                float q0 = __shfl_sync(0xffffffffu, p0, j);
                float q1 = __shfl_sync(0xffffffffu, p1, j);
                float ph = (lane < 16) ? q0 : q1;
                uint2 hv = HWh2[sj * 32 + lane];
                float2 f01 = __half22float2(*(__half2*)&hv.x);
                float2 f23 = __half22float2(*(__half2*)&hv.y);
                ax += ph * f01.x; ay += ph * f01.y; az += ph * f23.x; aw += ph * f23.y;
            }
        }
    }
#pragma unroll
    for (int o = 16; o > 0; o >>= 1) {
        sum0 += __shfl_xor_sync(0xffffffffu, sum0, o);
        sum1 += __shfl_xor_sync(0xffffffffu, sum1, o);
    }
    float inv = 1.f / ((lane < 16) ? sum0 : sum1);

    float4 hl = ((const float4*)g_HL)[node * 32 + lane];
    float4 gv = ((const float4*)gb)[lane];
    float4 o4;
    o4.x = fmaxf(hl.x + gv.x + ax * inv, 0.f);
    o4.y = fmaxf(hl.y + gv.y + ay * inv, 0.f);
    o4.z = fmaxf(hl.z + gv.z + az * inv, 0.f);
    o4.w = fmaxf(hl.w + gv.w + aw * inv, 0.f);
    ((float4*)g_H)[node * 32 + lane] = o4;
}

// ---------------- GAT edge phase, layer 3 (single-pass) ----------------
__global__ __launch_bounds__(256) void k_gat_edge3(const float* __restrict__ gb3,
                                                   float* __restrict__ out, int n) {
    int warp = (blockIdx.x * 256 + threadIdx.x) >> 5;
    int lane = threadIdx.x & 31;
    if (warp >= n) return;
    int node = warp;
    int beg = g_off[node], end = g_off[node + 1];
    float edv = g_ESDd[node].x;
    const float2* HW2 = (const float2*)g_HW;

    float sum = 0.f, a0 = 0.f, a1 = 0.f;
    for (int i = beg + lane; i < end; i += 32) {
        int s = g_csr[i];
        float p = __expf(leaky(g_ESDs[s].x + edv));
        float2 h = HW2[s];
        sum += p;
        a0 += p * h.x;
        a1 += p * h.y;
    }
#pragma unroll
    for (int o = 16; o > 0; o >>= 1) {
        sum += __shfl_xor_sync(0xffffffffu, sum, o);
        a0  += __shfl_xor_sync(0xffffffffu, a0, o);
        a1  += __shfl_xor_sync(0xffffffffu, a1, o);
    }
    if (lane == 0) {
        float inv = 1.f / sum;
        out[node * 2]     = fmaxf(g_HL[node * 2]     + gb3[0] + a0 * inv, 0.f);
        out[node * 2 + 1] = fmaxf(g_HL[node * 2 + 1] + gb3[1] + a1 * inv, 0.f);
    }
}

// ---------------- host launch ----------------
extern "C" void kernel_launch(void* const* d_in, const int* in_sizes, int n_in,
                              void* d_out, int out_size) {
    const float* x  = (const float*)d_in[0];
    const int*   ei = (const int*)d_in[1];
    const float *W1 = (const float*)d_in[2],  *as1 = (const float*)d_in[3],
                *ad1 = (const float*)d_in[4], *gb1 = (const float*)d_in[5],
                *lw1 = (const float*)d_in[6], *lb1 = (const float*)d_in[7],
                *bg1 = (const float*)d_in[8], *bb1 = (const float*)d_in[9];
    const float *W2 = (const float*)d_in[10], *as2 = (const float*)d_in[11],
                *ad2 = (const float*)d_in[12], *gb2 = (const float*)d_in[13],
                *lw2 = (const float*)d_in[14], *lb2 = (const float*)d_in[15],
                *bg2 = (const float*)d_in[16], *bb2 = (const float*)d_in[17];
    const float *W3 = (const float*)d_in[18], *as3 = (const float*)d_in[19],
                *ad3 = (const float*)d_in[20], *gb3 = (const float*)d_in[21],
                *lw3 = (const float*)d_in[22], *lb3 = (const float*)d_in[23],
                *bg3 = (const float*)d_in[24], *bb3 = (const float*)d_in[25];
    (void)n_in; (void)out_size;

    int n  = in_sizes[0] / 128;
    int E  = in_sizes[1] / 2;
    int ET = E + n;
    float* out = (float*)d_out;
    float inv_n = 1.f / (float)n;

    int eb = (ET + 255) / 256;
    dim3 gg((n + 127) / 128, 2);
    int wb = (n + 7) / 8;

    static int inited = 0;
    static cudaStream_t s1 = nullptr, s2 = nullptr;
    static cudaEvent_t ev_fork = nullptr, ev_p1 = nullptr, ev_p2 = nullptr, ev_csr = nullptr;
    if (!inited) {
        cudaFuncSetAttribute(k_gemm_mma, cudaFuncAttributeMaxDynamicSharedMemorySize, GEMM_SMEM);
        cudaStreamCreateWithFlags(&s1, cudaStreamNonBlocking);
        cudaStreamCreateWithFlags(&s2, cudaStreamNonBlocking);
        cudaEventCreateWithFlags(&ev_fork, cudaEventDisableTiming);
        cudaEventCreateWithFlags(&ev_p1, cudaEventDisableTiming);
        cudaEventCreateWithFlags(&ev_p2, cudaEventDisableTiming);
        cudaEventCreateWithFlags(&ev_csr, cudaEventDisableTiming);
        inited = 1;
    }

    // ---- fork side work ----
    cudaEventRecord(ev_fork, 0);
    cudaStreamWaitEvent(s1, ev_fork, 0);
    cudaStreamWaitEvent(s2, ev_fork, 0);

    // s1: weight preps (data-independent)
    k_prep12<<<131, 256, 0, s1>>>(0, W1, lw1, lb1, as1, ad1);
    cudaEventRecord(ev_p1, s1);
    k_prep12<<<131, 256, 0, s1>>>(1, W2, lw2, lb2, as2, ad2);
    cudaEventRecord(ev_p2, s1);

    // s2: CSR build — wide grids for latency-bound phases, small persistent scan
    k_zero_deg<<<(SCAN_N + 255) / 256, 256, 0, s2>>>();
    k_count<<<eb, 256, 0, s2>>>(ei, E, ET);
    k_scan<<<NSM, 256, 0, s2>>>(n, NSM);
    k_scatter<<<eb, 256, 0, s2>>>(ei, E, ET);
    cudaEventRecord(ev_csr, s2);

    // ---- main chain (9 nodes) ----
    k_bnr<<<NSM, 1024>>>(x, n * 128, bg1, bb1, inv_n, NSM);
    cudaStreamWaitEvent(0, ev_p1, 0);
    k_gemm_mma<<<gg, 256, GEMM_SMEM>>>(0, x, n);
    cudaStreamWaitEvent(0, ev_csr, 0);
    k_gat_edge12<<<wb, 256>>>(gb1, n);

    k_bnr<<<NSM, 1024>>>(nullptr, n * 128, bg2, bb2, inv_n, NSM);
    cudaStreamWaitEvent(0, ev_p2, 0);
    k_gemm_mma<<<gg, 256, GEMM_SMEM>>>(1, nullptr, n);
    k_gat_edge12<<<wb, 256>>>(gb2, n);

    k_bnr<<<NSM, 1024>>>(nullptr, n * 128, bg3, bb3, inv_n, NSM);
    k_gemv6<<<wb, 256>>>(W3, lw3, lb3, as3, ad3, n);
    k_gat_edge3<<<wb, 256>>>(gb3, out, n);
}

// round 15
// speedup vs baseline: 1.1202x; 1.0159x over previous
#include <cuda_runtime.h>
#include <cuda_bf16.h>
#include <cuda_fp16.h>
#include <cstdint>

#define LEAKY 0.2f
#define BN_EPS 1e-5f
#define MAXN 50000
#define MAXE 1600000
#define MAXET (MAXN + MAXE)
#define SCAN_N 50176
#define NBLK 196
#define NSM 148

// ---------------- device scratch ----------------
__device__ int   g_deg[SCAN_N];          // invariant: zero at graph entry (scan re-zeroes)
__device__ int   g_off[MAXN + 1];
__device__ int   g_cursor[MAXN];
__device__ int   g_csr[MAXET];
__device__ int   g_bsum[256];
__device__ float g_red[NSM * 256];
__device__ float g_scale[128];
__device__ float g_shift[128];
__device__ float g_HW[MAXN * 2];        // layer-3 head features (fp32)
__device__ __half g_HWh[MAXN * 128];    // layer-1/2 head features (fp16 gather payload)
__device__ float g_HL[MAXN * 128];
__device__ float2 g_ESDs[MAXN];         // per-src attention terms (es0, es1)
__device__ float2 g_ESDd[MAXN];         // per-dst attention terms (ed0, ed1)
__device__ float g_H[MAXN * 128];
// double-buffered per-layer weights
__device__ __nv_bfloat16 g_Bhi[2][256 * 128];   // [n][k]
__device__ __nv_bfloat16 g_Blo[2][256 * 128];
__device__ float g_bcatL[2][256];
__device__ float g_wesd[2][512];                // [k][4]

// ---------------- software grid barriers (separate slots: bnr vs scan) -------------
__device__ unsigned g_bcount = 0, g_bgen = 0;      // k_bnr
__device__ unsigned g_ccount = 0, g_cgen = 0;      // k_scan

__device__ __forceinline__ void grid_sync_slot(unsigned* cnt, unsigned* gen, int nb) {
    __syncthreads();
    if (threadIdx.x == 0) {
        unsigned my = *((volatile unsigned*)gen);
        __threadfence();
        unsigned old = atomicAdd(cnt, 1);
        if (old == (unsigned)nb - 1) {
            *cnt = 0;
            __threadfence();
            atomicAdd(gen, 1);
        } else {
            while (*((volatile unsigned*)gen) == my) { __nanosleep(64); }
            __threadfence();
        }
    }
    __syncthreads();
}

// ---------------- CSR build ----------------
__global__ void k_count(const int* __restrict__ ei, int E, int ET) {
    int i = blockIdx.x * 256 + threadIdx.x;
    if (i < ET) {
        int d = (i < E) ? ei[E + i] : (i - E);
        atomicAdd(&g_deg[d], 1);
    }
}
__global__ __launch_bounds__(256) void k_scan(int n, int nb) {
    __shared__ int sh[256];
    int tid = threadIdx.x, bid = blockIdx.x;

    for (int b = bid; b < NBLK; b += nb) {
        sh[tid] = g_deg[b * 256 + tid];
        __syncthreads();
        for (int o = 128; o > 0; o >>= 1) {
            if (tid < o) sh[tid] += sh[tid + o];
            __syncthreads();
        }
        if (tid == 0) g_bsum[b] = sh[0];
        __syncthreads();
    }
    grid_sync_slot(&g_ccount, &g_cgen, nb);

    if (bid == 0) {
        int v = (tid < NBLK) ? g_bsum[tid] : 0;
        sh[tid] = v;
        __syncthreads();
        for (int o = 1; o < 256; o <<= 1) {
            int t = (tid >= o) ? sh[tid - o] : 0;
            __syncthreads();
            sh[tid] += t;
            __syncthreads();
        }
        if (tid < NBLK) g_bsum[tid] = sh[tid] - v;
    }
    grid_sync_slot(&g_ccount, &g_cgen, nb);

    for (int b = bid; b < NBLK; b += nb) {
        int gi = b * 256 + tid;
        int v = g_deg[gi];
        g_deg[gi] = 0;                     // restore zero-invariant for next replay
        sh[tid] = v;
        __syncthreads();
        for (int o = 1; o < 256; o <<= 1) {
            int t = (tid >= o) ? sh[tid - o] : 0;
            __syncthreads();
            sh[tid] += t;
            __syncthreads();
        }
        int ex = sh[tid] - v + g_bsum[b];
        if (gi <= n) g_off[gi] = ex;
        if (gi < n)  g_cursor[gi] = ex;
        __syncthreads();
    }
}
__global__ void k_scatter(const int* __restrict__ ei, int E, int ET) {
    int i = blockIdx.x * 256 + threadIdx.x;
    if (i < ET) {
        int s, d;
        if (i < E) { s = ei[i]; d = ei[E + i]; }
        else       { s = d = i - E; }
        g_csr[atomicAdd(&g_cursor[d], 1)] = s;
    }
}

// ---------------- BN stats: 1024-thr blocks, 148 arrivals, float4 streaming --------
__global__ __launch_bounds__(1024) void k_bnr(const float* __restrict__ A, int total,
                                              const float* __restrict__ bg,
                                              const float* __restrict__ bb,
                                              float inv_n, int nb) {
    const float4* H4 = (const float4*)(A ? A : g_H);
    __shared__ float4 ss[1024], qq[1024];
    int tid = threadIdx.x, bid = blockIdx.x;
    int total4 = total >> 2;
    float4 s = {0.f, 0.f, 0.f, 0.f}, q = {0.f, 0.f, 0.f, 0.f};
    for (int e = bid * 1024 + tid; e < total4; e += nb * 1024) {
        float4 v = H4[e];
        s.x += v.x; s.y += v.y; s.z += v.z; s.w += v.w;
        q.x += v.x * v.x; q.y += v.y * v.y; q.z += v.z * v.z; q.w += v.w * v.w;
    }
    ss[tid] = s; qq[tid] = q;
    __syncthreads();
    if (tid < 32) {
        float4 S = ss[tid], Q = qq[tid];
        for (int t = tid + 32; t < 1024; t += 32) {
            float4 a = ss[t], b = qq[t];
            S.x += a.x; S.y += a.y; S.z += a.z; S.w += a.w;
            Q.x += b.x; Q.y += b.y; Q.z += b.z; Q.w += b.w;
        }
        int c = tid * 4;
        g_red[bid * 256 + c]     = S.x;
        g_red[bid * 256 + c + 1] = S.y;
        g_red[bid * 256 + c + 2] = S.z;
        g_red[bid * 256 + c + 3] = S.w;
        g_red[bid * 256 + 128 + c]     = Q.x;
        g_red[bid * 256 + 128 + c + 1] = Q.y;
        g_red[bid * 256 + 128 + c + 2] = Q.z;
        g_red[bid * 256 + 128 + c + 3] = Q.w;
    }
    grid_sync_slot(&g_bcount, &g_bgen, nb);
    if (bid == 0 && tid < 128) {
        float s2 = 0.f, q2 = 0.f;
        for (int b = 0; b < nb; b++) {
            s2 += g_red[b * 256 + tid];
            q2 += g_red[b * 256 + 128 + tid];
        }
        float mu  = s2 * inv_n;
        float var = q2 * inv_n - mu * mu;
        float sc  = bg[tid] * rsqrtf(var + BN_EPS);
        g_scale[tid] = sc;
        g_shift[tid] = bb[tid] - mu * sc;
    }
}

// ---------------- weight prep (side stream, data-independent) ----------------
__global__ void k_prep12(int l, const float* __restrict__ W, const float* __restrict__ lw,
                         const float* __restrict__ lb, const float* __restrict__ as,
                         const float* __restrict__ ad) {
    int idx = blockIdx.x * 256 + threadIdx.x;
    if (idx >= 128 * 260) return;
    int k = idx / 260, j = idx % 260;
    float v;
    if (j < 128)       v = W[k * 128 + j];
    else if (j < 256)  v = lw[k * 128 + (j - 128)];
    else {
        int t = j - 256;
        int hh = t & 1;
        const float* a = (t < 2) ? as : ad;
        float s = 0.f;
        for (int f = 0; f < 64; f++) s += W[k * 128 + hh * 64 + f] * a[hh * 64 + f];
        v = s;
    }
    if (j < 256) {
        __nv_bfloat16 h = __float2bfloat16(v);
        g_Bhi[l][j * 128 + k] = h;
        g_Blo[l][j * 128 + k] = __float2bfloat16(v - __bfloat162float(h));
        if (k == 0) g_bcatL[l][j] = (j >= 128) ? lb[j - 128] : 0.f;
    } else {
        g_wesd[l][k * 4 + (j - 256)] = v;
    }
}

// ---------------- mma helpers ----------------
__device__ __forceinline__ uint32_t smem_u32(const void* p) {
    uint32_t a;
    asm("{ .reg .u64 t; cvta.to.shared.u64 t, %1; cvt.u32.u64 %0, t; }" : "=r"(a) : "l"(p));
    return a;
}
__device__ __forceinline__ void ldsm_x4(uint32_t* r, uint32_t addr) {
    asm volatile("ldmatrix.sync.aligned.m8n8.x4.shared.b16 {%0,%1,%2,%3}, [%4];"
        : "=r"(r[0]), "=r"(r[1]), "=r"(r[2]), "=r"(r[3]) : "r"(addr));
}
__device__ __forceinline__ void ldsm_x2(uint32_t* r, uint32_t addr) {
    asm volatile("ldmatrix.sync.aligned.m8n8.x2.shared.b16 {%0,%1}, [%2];"
        : "=r"(r[0]), "=r"(r[1]) : "r"(addr));
}
__device__ __forceinline__ void mma_bf16(float* d, const uint32_t* a, const uint32_t* b) {
    asm volatile("mma.sync.aligned.m16n8k16.row.col.f32.bf16.bf16.f32 "
        "{%0,%1,%2,%3}, {%4,%5,%6,%7}, {%8,%9}, {%0,%1,%2,%3};"
        : "+f"(d[0]), "+f"(d[1]), "+f"(d[2]), "+f"(d[3])
        : "r"(a[0]), "r"(a[1]), "r"(a[2]), "r"(a[3]), "r"(b[0]), "r"(b[1]));
}
__device__ __forceinline__ float leaky(float x) { return (x > 0.f) ? x : LEAKY * x; }

// ---------------- tensor-core GEMM + fused esd ----------------
#define APAD 136
#define TILE_BYTES (128 * APAD * 2)
#define GEMM_SMEM  (4 * TILE_BYTES + 2048)

__global__ __launch_bounds__(256, 1) void k_gemm_mma(int l, const float* __restrict__ Ain, int M) {
    const float* A = Ain ? Ain : g_H;
    extern __shared__ char sm[];
    __nv_bfloat16* sAhi = (__nv_bfloat16*)sm;
    __nv_bfloat16* sAlo = (__nv_bfloat16*)(sm + TILE_BYTES);
    __nv_bfloat16* sBhi = (__nv_bfloat16*)(sm + 2 * TILE_BYTES);
    __nv_bfloat16* sBlo = (__nv_bfloat16*)(sm + 3 * TILE_BYTES);
    float* wesd = (float*)(sm + 4 * TILE_BYTES);

    int tid = threadIdx.x, lane = tid & 31, wid = tid >> 5;
    int warp_m = wid & 1;
    int warp_n = wid >> 1;
    int m0 = blockIdx.x * 128;
    int n0 = blockIdx.y * 128;

    for (int idx = tid; idx < 4096; idx += 256) {
        int row = idx >> 5, c = (idx & 31) * 4;
        int gm = m0 + row;
        float4 t = (gm < M) ? *(const float4*)(A + gm * 128 + c)
                            : make_float4(0.f, 0.f, 0.f, 0.f);
        float v0 = t.x * g_scale[c]     + g_shift[c];
        float v1 = t.y * g_scale[c + 1] + g_shift[c + 1];
        float v2 = t.z * g_scale[c + 2] + g_shift[c + 2];
        float v3 = t.w * g_scale[c + 3] + g_shift[c + 3];
        if (gm >= M) { v0 = v1 = v2 = v3 = 0.f; }
        __nv_bfloat16 h0 = __float2bfloat16(v0), h1 = __float2bfloat16(v1);
        __nv_bfloat16 h2 = __float2bfloat16(v2), h3 = __float2bfloat16(v3);
        __nv_bfloat162 hp0(h0, h1), hp1(h2, h3);
        __nv_bfloat162 lp0(__float2bfloat16(v0 - __bfloat162float(h0)),
                           __float2bfloat16(v1 - __bfloat162float(h1)));
        __nv_bfloat162 lp1(__float2bfloat16(v2 - __bfloat162float(h2)),
                           __float2bfloat16(v3 - __bfloat162float(h3)));
        int o = row * APAD + c;
        *(__nv_bfloat162*)(sAhi + o)     = hp0;
        *(__nv_bfloat162*)(sAhi + o + 2) = hp1;
        *(__nv_bfloat162*)(sAlo + o)     = lp0;
        *(__nv_bfloat162*)(sAlo + o + 2) = lp1;
    }
    for (int idx = tid; idx < 2048; idx += 256) {
        int row = idx >> 4, c = (idx & 15) * 8;
        int gn = n0 + row;
        uint4 hv = *(const uint4*)(g_Bhi[l] + gn * 128 + c);
        uint4 lv = *(const uint4*)(g_Blo[l] + gn * 128 + c);
        int o = row * APAD + c;
        *(uint4*)(sBhi + o) = hv;
        *(uint4*)(sBlo + o) = lv;
    }
    if (blockIdx.y == 1)
        for (int i = tid; i < 512; i += 256) wesd[i] = g_wesd[l][i];
    __syncthreads();

    int rA = lane & 15, cA = (lane >> 4) * 8;
    int rB = lane & 7,  cB = ((lane >> 3) & 1) * 8;
    uint32_t baseAhi[4], baseAlo[4], baseBhi[4], baseBlo[4];
#pragma unroll
    for (int mt = 0; mt < 4; mt++) {
        int row = warp_m * 64 + mt * 16 + rA;
        baseAhi[mt] = smem_u32(sAhi + row * APAD + cA);
        baseAlo[mt] = smem_u32(sAlo + row * APAD + cA);
    }
#pragma unroll
    for (int nt = 0; nt < 4; nt++) {
        int row = warp_n * 32 + nt * 8 + rB;
        baseBhi[nt] = smem_u32(sBhi + row * APAD + cB);
        baseBlo[nt] = smem_u32(sBlo + row * APAD + cB);
    }

    float acc[4][4][4] = {};
#pragma unroll
    for (int ks = 0; ks < 8; ks++) {
        uint32_t koff = ks * 32;
        uint32_t ahi[4][4], alo[4][4], bhi[4][2], blo[4][2];
#pragma unroll
        for (int mt = 0; mt < 4; mt++) {
            ldsm_x4(ahi[mt], baseAhi[mt] + koff);
            ldsm_x4(alo[mt], baseAlo[mt] + koff);
        }
#pragma unroll
        for (int nt = 0; nt < 4; nt++) {
            ldsm_x2(bhi[nt], baseBhi[nt] + koff);
            ldsm_x2(blo[nt], baseBlo[nt] + koff);
        }
#pragma unroll
        for (int mt = 0; mt < 4; mt++)
#pragma unroll
            for (int nt = 0; nt < 4; nt++) {
                mma_bf16(acc[mt][nt], ahi[mt], bhi[nt]);
                mma_bf16(acc[mt][nt], ahi[mt], blo[nt]);
                mma_bf16(acc[mt][nt], alo[mt], bhi[nt]);
            }
    }

    // ---- epilogue ----
#pragma unroll
    for (int mt = 0; mt < 4; mt++) {
        int gm0 = m0 + warp_m * 64 + mt * 16 + (lane >> 2);
#pragma unroll
        for (int nt = 0; nt < 4; nt++) {
            int col = warp_n * 32 + nt * 8 + (lane & 3) * 2;
            float b0 = g_bcatL[l][n0 + col], b1 = g_bcatL[l][n0 + col + 1];
            if (blockIdx.y == 0) {
                if (gm0 < M)
                    *(__half2*)(g_HWh + gm0 * 128 + col) =
                        __floats2half2_rn(acc[mt][nt][0] + b0, acc[mt][nt][1] + b1);
                if (gm0 + 8 < M)
                    *(__half2*)(g_HWh + (gm0 + 8) * 128 + col) =
                        __floats2half2_rn(acc[mt][nt][2] + b0, acc[mt][nt][3] + b1);
            } else {
                if (gm0 < M) {
                    float2 v = {acc[mt][nt][0] + b0, acc[mt][nt][1] + b1};
                    *(float2*)(g_HL + gm0 * 128 + col) = v;
                }
                if (gm0 + 8 < M) {
                    float2 v = {acc[mt][nt][2] + b0, acc[mt][nt][3] + b1};
                    *(float2*)(g_HL + (gm0 + 8) * 128 + col) = v;
                }
            }
        }
    }

    if (blockIdx.y == 1) {
        for (int r = 0; r < 16; r++) {
            int row = wid * 16 + r;
            int gm = m0 + row;
            int k = lane * 4;
            int o = row * APAD + k;
            float a0 = __bfloat162float(sAhi[o])     + __bfloat162float(sAlo[o]);
            float a1 = __bfloat162float(sAhi[o + 1]) + __bfloat162float(sAlo[o + 1]);
            float a2 = __bfloat162float(sAhi[o + 2]) + __bfloat162float(sAlo[o + 2]);
            float a3 = __bfloat162float(sAhi[o + 3]) + __bfloat162float(sAlo[o + 3]);
            float s0 = a0 * wesd[k * 4]     + a1 * wesd[(k + 1) * 4]     + a2 * wesd[(k + 2) * 4]     + a3 * wesd[(k + 3) * 4];
            float s1 = a0 * wesd[k * 4 + 1] + a1 * wesd[(k + 1) * 4 + 1] + a2 * wesd[(k + 2) * 4 + 1] + a3 * wesd[(k + 3) * 4 + 1];
            float s2 = a0 * wesd[k * 4 + 2] + a1 * wesd[(k + 1) * 4 + 2] + a2 * wesd[(k + 2) * 4 + 2] + a3 * wesd[(k + 3) * 4 + 2];
            float s3 = a0 * wesd[k * 4 + 3] + a1 * wesd[(k + 1) * 4 + 3] + a2 * wesd[(k + 2) * 4 + 3] + a3 * wesd[(k + 3) * 4 + 3];
#pragma unroll
            for (int sh = 16; sh > 0; sh >>= 1) {
                s0 += __shfl_xor_sync(0xffffffffu, s0, sh);
                s1 += __shfl_xor_sync(0xffffffffu, s1, sh);
                s2 += __shfl_xor_sync(0xffffffffu, s2, sh);
                s3 += __shfl_xor_sync(0xffffffffu, s3, sh);
            }
            if (lane == 0 && gm < M) {
                g_ESDs[gm] = make_float2(s0, s1);
                g_ESDd[gm] = make_float2(s2, s3);
            }
        }
    }
}

// ---------------- layer 3 GEMV (self-prep weights) ----------------
__global__ __launch_bounds__(256) void k_gemv6(const float* __restrict__ W3,
                                               const float* __restrict__ lw3,
                                               const float* __restrict__ lb3,
                                               const float* __restrict__ as3,
                                               const float* __restrict__ ad3,
                                               int n) {
    const float* A = g_H;
    __shared__ float ws[768];
    __shared__ float bs[8];
    int tid = threadIdx.x;
    for (int i = tid; i < 768; i += 256) {
        int k = i / 6, j = i % 6;
        float v;
        if (j < 2)      v = W3[k * 2 + j];
        else if (j < 4) v = lw3[k * 2 + (j - 2)];
        else {
            const float* a = (j == 4) ? as3 : ad3;
            v = W3[k * 2] * a[0] + W3[k * 2 + 1] * a[1];
        }
        ws[i] = v;
    }
    if (tid < 2) bs[tid] = lb3[tid];
    __syncthreads();
    int row = blockIdx.x * 8 + (tid >> 5);
    int lane = tid & 31;
    if (row >= n) return;
    float4 a = ((const float4*)A)[row * 32 + lane];
    int k = lane * 4;
    float a0 = a.x * g_scale[k]     + g_shift[k];
    float a1 = a.y * g_scale[k + 1] + g_shift[k + 1];
    float a2 = a.z * g_scale[k + 2] + g_shift[k + 2];
    float a3 = a.w * g_scale[k + 3] + g_shift[k + 3];
    float c[6];
#pragma unroll
    for (int j = 0; j < 6; j++)
        c[j] = a0 * ws[k * 6 + j] + a1 * ws[(k + 1) * 6 + j] +
               a2 * ws[(k + 2) * 6 + j] + a3 * ws[(k + 3) * 6 + j];
#pragma unroll
    for (int j = 0; j < 6; j++)
#pragma unroll
        for (int o = 16; o > 0; o >>= 1) c[j] += __shfl_xor_sync(0xffffffffu, c[j], o);
    if (lane == 0) {
        g_HW[row * 2]     = c[0];
        g_HW[row * 2 + 1] = c[1];
        g_HL[row * 2]     = c[2] + bs[0];
        g_HL[row * 2 + 1] = c[3] + bs[1];
        g_ESDs[row] = make_float2(c[4], 0.f);
        g_ESDd[row] = make_float2(c[5], 0.f);
    }
}

// ---------------- GAT edge phase, layers 1/2 (single-pass, fp16 gather, 2-shfl) ----
__global__ __launch_bounds__(256) void k_gat_edge12(const float* __restrict__ gb, int n) {
    int warp = (blockIdx.x * 256 + threadIdx.x) >> 5;
    int lane = threadIdx.x & 31;
    if (warp >= n) return;
    int node = warp;
    int beg = g_off[node], end = g_off[node + 1];
    float2 ed = g_ESDd[node];
    const uint2* HWh2 = (const uint2*)g_HWh;

    float sum0 = 0.f, sum1 = 0.f;
    float ax = 0.f, ay = 0.f, az = 0.f, aw = 0.f;
    for (int base = beg; base < end; base += 32) {
        int i = base + lane;
        int s = 0;
        float p0 = 0.f, p1 = 0.f;
        if (i < end) {
            s = g_csr[i];
            float2 e = g_ESDs[s];
            p0 = __expf(leaky(e.x + ed.x));
            p1 = __expf(leaky(e.y + ed.y));
        }
        sum0 += p0; sum1 += p1;
        // pack p0,p1 into half2 for single-shfl broadcast
        __half2 ph2 = __floats2half2_rn(p0, p1);
        uint32_t ppack = *(uint32_t*)&ph2;
        int cnt = min(32, end - base);
        if (cnt == 32) {
#pragma unroll
            for (int j = 0; j < 32; j++) {
                int sj    = __shfl_sync(0xffffffffu, s, j);
                uint32_t qp = __shfl_sync(0xffffffffu, ppack, j);
                float2 pq = __half22float2(*(__half2*)&qp);
                float ph = (lane < 16) ? pq.x : pq.y;
                uint2 hv = HWh2[sj * 32 + lane];
                float2 f01 = __half22float2(*(__half2*)&hv.x);
                float2 f23 = __half22float2(*(__half2*)&hv.y);
                ax += ph * f01.x; ay += ph * f01.y; az += ph * f23.x; aw += ph * f23.y;
            }
        } else {
            for (int j = 0; j < cnt; j++) {
                int sj    = __shfl_sync(0xffffffffu, s, j);
                uint32_t qp = __shfl_sync(0xffffffffu, ppack, j);
                float2 pq = __half22float2(*(__half2*)&qp);
                float ph = (lane < 16) ? pq.x : pq.y;
                uint2 hv = HWh2[sj * 32 + lane];
                float2 f01 = __half22float2(*(__half2*)&hv.x);
                float2 f23 = __half22float2(*(__half2*)&hv.y);
                ax += ph * f01.x; ay += ph * f01.y; az += ph * f23.x; aw += ph * f23.y;
            }
        }
    }
#pragma unroll
    for (int o = 16; o > 0; o >>= 1) {
        sum0 += __shfl_xor_sync(0xffffffffu, sum0, o);
        sum1 += __shfl_xor_sync(0xffffffffu, sum1, o);
    }
    float inv = 1.f / ((lane < 16) ? sum0 : sum1);

    float4 hl = ((const float4*)g_HL)[node * 32 + lane];
    float4 gv = ((const float4*)gb)[lane];
    float4 o4;
    o4.x = fmaxf(hl.x + gv.x + ax * inv, 0.f);
    o4.y = fmaxf(hl.y + gv.y + ay * inv, 0.f);
    o4.z = fmaxf(hl.z + gv.z + az * inv, 0.f);
    o4.w = fmaxf(hl.w + gv.w + aw * inv, 0.f);
    ((float4*)g_H)[node * 32 + lane] = o4;
}

// ---------------- GAT edge phase, layer 3 (single-pass) ----------------
__global__ __launch_bounds__(256) void k_gat_edge3(const float* __restrict__ gb3,
                                                   float* __restrict__ out, int n) {
    int warp = (blockIdx.x * 256 + threadIdx.x) >> 5;
    int lane = threadIdx.x & 31;
    if (warp >= n) return;
    int node = warp;
    int beg = g_off[node], end = g_off[node + 1];
    float edv = g_ESDd[node].x;
    const float2* HW2 = (const float2*)g_HW;

    float sum = 0.f, a0 = 0.f, a1 = 0.f;
    for (int i = beg + lane; i < end; i += 32) {
        int s = g_csr[i];
        float p = __expf(leaky(g_ESDs[s].x + edv));
        float2 h = HW2[s];
        sum += p;
        a0 += p * h.x;
        a1 += p * h.y;
    }
#pragma unroll
    for (int o = 16; o > 0; o >>= 1) {
        sum += __shfl_xor_sync(0xffffffffu, sum, o);
        a0  += __shfl_xor_sync(0xffffffffu, a0, o);
        a1  += __shfl_xor_sync(0xffffffffu, a1, o);
    }
    if (lane == 0) {
        float inv = 1.f / sum;
        out[node * 2]     = fmaxf(g_HL[node * 2]     + gb3[0] + a0 * inv, 0.f);
        out[node * 2 + 1] = fmaxf(g_HL[node * 2 + 1] + gb3[1] + a1 * inv, 0.f);
    }
}

// ---------------- host launch ----------------
extern "C" void kernel_launch(void* const* d_in, const int* in_sizes, int n_in,
                              void* d_out, int out_size) {
    const float* x  = (const float*)d_in[0];
    const int*   ei = (const int*)d_in[1];
    const float *W1 = (const float*)d_in[2],  *as1 = (const float*)d_in[3],
                *ad1 = (const float*)d_in[4], *gb1 = (const float*)d_in[5],
                *lw1 = (const float*)d_in[6], *lb1 = (const float*)d_in[7],
                *bg1 = (const float*)d_in[8], *bb1 = (const float*)d_in[9];
    const float *W2 = (const float*)d_in[10], *as2 = (const float*)d_in[11],
                *ad2 = (const float*)d_in[12], *gb2 = (const float*)d_in[13],
                *lw2 = (const float*)d_in[14], *lb2 = (const float*)d_in[15],
                *bg2 = (const float*)d_in[16], *bb2 = (const float*)d_in[17];
    const float *W3 = (const float*)d_in[18], *as3 = (const float*)d_in[19],
                *ad3 = (const float*)d_in[20], *gb3 = (const float*)d_in[21],
                *lw3 = (const float*)d_in[22], *lb3 = (const float*)d_in[23],
                *bg3 = (const float*)d_in[24], *bb3 = (const float*)d_in[25];
    (void)n_in; (void)out_size;

    int n  = in_sizes[0] / 128;
    int E  = in_sizes[1] / 2;
    int ET = E + n;
    float* out = (float*)d_out;
    float inv_n = 1.f / (float)n;

    int eb = (ET + 255) / 256;
    dim3 gg((n + 127) / 128, 2);
    int wb = (n + 7) / 8;

    static int inited = 0;
    static cudaStream_t s1 = nullptr, s2 = nullptr;
    static cudaEvent_t ev_fork = nullptr, ev_p1 = nullptr, ev_p2 = nullptr, ev_csr = nullptr;
    if (!inited) {
        cudaFuncSetAttribute(k_gemm_mma, cudaFuncAttributeMaxDynamicSharedMemorySize, GEMM_SMEM);
        cudaStreamCreateWithFlags(&s1, cudaStreamNonBlocking);
        cudaStreamCreateWithFlags(&s2, cudaStreamNonBlocking);
        cudaEventCreateWithFlags(&ev_fork, cudaEventDisableTiming);
        cudaEventCreateWithFlags(&ev_p1, cudaEventDisableTiming);
        cudaEventCreateWithFlags(&ev_p2, cudaEventDisableTiming);
        cudaEventCreateWithFlags(&ev_csr, cudaEventDisableTiming);
        inited = 1;
    }

    // ---- fork side streams ----
    cudaEventRecord(ev_fork, 0);
    cudaStreamWaitEvent(s1, ev_fork, 0);
    cudaStreamWaitEvent(s2, ev_fork, 0);

    // launch 1: edge count (g_deg pre-zeroed invariant)
    k_count<<<eb, 256, 0, s2>>>(ei, E, ET);

    // launch 2: layer-1 weight prep
    k_prep12<<<131, 256, 0, s1>>>(0, W1, lw1, lb1, as1, ad1);
    cudaEventRecord(ev_p1, s1);

    // launch 3: layer-1 BN stats (main)
    k_bnr<<<NSM, 1024>>>(x, n * 128, bg1, bb1, inv_n, NSM);

    // launch 4: layer-1 GEMM (main)  <-- profiled by ncu
    cudaStreamWaitEvent(0, ev_p1, 0);
    k_gemm_mma<<<gg, 256, GEMM_SMEM>>>(0, x, n);

    // launches 5-6: CSR scan (+re-zero) and scatter (s2)
    k_scan<<<NSM, 256, 0, s2>>>(n, NSM);
    k_scatter<<<eb, 256, 0, s2>>>(ei, E, ET);
    cudaEventRecord(ev_csr, s2);

    // launch 7: layer-2 weight prep (s1)
    k_prep12<<<131, 256, 0, s1>>>(1, W2, lw2, lb2, as2, ad2);
    cudaEventRecord(ev_p2, s1);

    // launch 8: layer-1 edge phase (main)
    cudaStreamWaitEvent(0, ev_csr, 0);
    k_gat_edge12<<<wb, 256>>>(gb1, n);

    // layer 2
    k_bnr<<<NSM, 1024>>>(nullptr, n * 128, bg2, bb2, inv_n, NSM);
    cudaStreamWaitEvent(0, ev_p2, 0);
    k_gemm_mma<<<gg, 256, GEMM_SMEM>>>(1, nullptr, n);
    k_gat_edge12<<<wb, 256>>>(gb2, n);

    // layer 3
    k_bnr<<<NSM, 1024>>>(nullptr, n * 128, bg3, bb3, inv_n, NSM);
    k_gemv6<<<wb, 256>>>(W3, lw3, lb3, as3, ad3, n);
    k_gat_edge3<<<wb, 256>>>(gb3, out, n);
}

// round 16
// speedup vs baseline: 1.3013x; 1.1616x over previous
#include <cuda_runtime.h>
#include <cuda_bf16.h>
#include <cuda_fp16.h>
#include <cstdint>

#define LEAKY 0.2f
#define BN_EPS 1e-5f
#define MAXN 50000
#define MAXE 1600000
#define MAXET (MAXN + MAXE)
#define SCAN_N 50176
#define NBLK 196
#define NSM 148

// ---------------- device scratch ----------------
__device__ int   g_deg[SCAN_N];          // invariant: zero at graph entry (scan re-zeroes)
__device__ int   g_off[MAXN + 1];
__device__ int   g_cursor[MAXN];
__device__ int   g_csr[MAXET];
__device__ int   g_bsum[256];
__device__ float g_red[NSM * 256];
__device__ float g_scale[128];
__device__ float g_shift[128];
__device__ float g_HW[MAXN * 2];        // layer-3 head features (fp32)
__device__ __half g_HWh[MAXN * 128];    // layer-1/2 head features (fp16 gather payload)
__device__ float g_HL[MAXN * 128];
__device__ float2 g_ESDs[MAXN];
__device__ float2 g_ESDd[MAXN];
__device__ float g_H[MAXN * 128];
__device__ __nv_bfloat16 g_Bhi[2][256 * 128];   // [n][k]
__device__ __nv_bfloat16 g_Blo[2][256 * 128];
__device__ float g_bcatL[2][256];
__device__ float g_wesd[2][512];                // [k][4]

// ---------------- software grid barriers ----------------
__device__ unsigned g_bcount = 0, g_bgen = 0;      // k_bnr
__device__ unsigned g_ccount = 0, g_cgen = 0;      // k_scan

__device__ __forceinline__ void grid_sync_slot(unsigned* cnt, unsigned* gen, int nb) {
    __syncthreads();
    if (threadIdx.x == 0) {
        unsigned my = *((volatile unsigned*)gen);
        __threadfence();
        unsigned old = atomicAdd(cnt, 1);
        if (old == (unsigned)nb - 1) {
            *cnt = 0;
            __threadfence();
            atomicAdd(gen, 1);
        } else {
            while (*((volatile unsigned*)gen) == my) { __nanosleep(64); }
            __threadfence();
        }
    }
    __syncthreads();
}

// ---------------- CSR build ----------------
__global__ void k_count(const int* __restrict__ ei, int E, int ET) {
    int i = blockIdx.x * 256 + threadIdx.x;
    if (i < ET) {
        int d = (i < E) ? ei[E + i] : (i - E);
        atomicAdd(&g_deg[d], 1);
    }
}
__global__ __launch_bounds__(256) void k_scan(int n, int nb) {
    __shared__ int sh[256];
    int tid = threadIdx.x, bid = blockIdx.x;

    for (int b = bid; b < NBLK; b += nb) {
        sh[tid] = g_deg[b * 256 + tid];
        __syncthreads();
        for (int o = 128; o > 0; o >>= 1) {
            if (tid < o) sh[tid] += sh[tid + o];
            __syncthreads();
        }
        if (tid == 0) g_bsum[b] = sh[0];
        __syncthreads();
    }
    grid_sync_slot(&g_ccount, &g_cgen, nb);

    if (bid == 0) {
        int v = (tid < NBLK) ? g_bsum[tid] : 0;
        sh[tid] = v;
        __syncthreads();
        for (int o = 1; o < 256; o <<= 1) {
            int t = (tid >= o) ? sh[tid - o] : 0;
            __syncthreads();
            sh[tid] += t;
            __syncthreads();
        }
        if (tid < NBLK) g_bsum[tid] = sh[tid] - v;
    }
    grid_sync_slot(&g_ccount, &g_cgen, nb);

    for (int b = bid; b < NBLK; b += nb) {
        int gi = b * 256 + tid;
        int v = g_deg[gi];
        g_deg[gi] = 0;
        sh[tid] = v;
        __syncthreads();
        for (int o = 1; o < 256; o <<= 1) {
            int t = (tid >= o) ? sh[tid - o] : 0;
            __syncthreads();
            sh[tid] += t;
            __syncthreads();
        }
        int ex = sh[tid] - v + g_bsum[b];
        if (gi <= n) g_off[gi] = ex;
        if (gi < n)  g_cursor[gi] = ex;
        __syncthreads();
    }
}
__global__ void k_scatter(const int* __restrict__ ei, int E, int ET) {
    int i = blockIdx.x * 256 + threadIdx.x;
    if (i < ET) {
        int s, d;
        if (i < E) { s = ei[i]; d = ei[E + i]; }
        else       { s = d = i - E; }
        g_csr[atomicAdd(&g_cursor[d], 1)] = s;
    }
}

// ---------------- BN stats ----------------
__global__ __launch_bounds__(1024) void k_bnr(const float* __restrict__ A, int total,
                                              const float* __restrict__ bg,
                                              const float* __restrict__ bb,
                                              float inv_n, int nb) {
    const float4* H4 = (const float4*)(A ? A : g_H);
    __shared__ float4 ss[1024], qq[1024];
    int tid = threadIdx.x, bid = blockIdx.x;
    int total4 = total >> 2;
    float4 s = {0.f, 0.f, 0.f, 0.f}, q = {0.f, 0.f, 0.f, 0.f};
    for (int e = bid * 1024 + tid; e < total4; e += nb * 1024) {
        float4 v = H4[e];
        s.x += v.x; s.y += v.y; s.z += v.z; s.w += v.w;
        q.x += v.x * v.x; q.y += v.y * v.y; q.z += v.z * v.z; q.w += v.w * v.w;
    }
    ss[tid] = s; qq[tid] = q;
    __syncthreads();
    if (tid < 32) {
        float4 S = ss[tid], Q = qq[tid];
        for (int t = tid + 32; t < 1024; t += 32) {
            float4 a = ss[t], b = qq[t];
            S.x += a.x; S.y += a.y; S.z += a.z; S.w += a.w;
            Q.x += b.x; Q.y += b.y; Q.z += b.z; Q.w += b.w;
        }
        int c = tid * 4;
        g_red[bid * 256 + c]     = S.x;
        g_red[bid * 256 + c + 1] = S.y;
        g_red[bid * 256 + c + 2] = S.z;
        g_red[bid * 256 + c + 3] = S.w;
        g_red[bid * 256 + 128 + c]     = Q.x;
        g_red[bid * 256 + 128 + c + 1] = Q.y;
        g_red[bid * 256 + 128 + c + 2] = Q.z;
        g_red[bid * 256 + 128 + c + 3] = Q.w;
    }
    grid_sync_slot(&g_bcount, &g_bgen, nb);
    if (bid == 0 && tid < 128) {
        float s2 = 0.f, q2 = 0.f;
        for (int b = 0; b < nb; b++) {
            s2 += g_red[b * 256 + tid];
            q2 += g_red[b * 256 + 128 + tid];
        }
        float mu  = s2 * inv_n;
        float var = q2 * inv_n - mu * mu;
        float sc  = bg[tid] * rsqrtf(var + BN_EPS);
        g_scale[tid] = sc;
        g_shift[tid] = bb[tid] - mu * sc;
    }
}

// ---------------- weight prep ----------------
__global__ void k_prep12(int l, const float* __restrict__ W, const float* __restrict__ lw,
                         const float* __restrict__ lb, const float* __restrict__ as,
                         const float* __restrict__ ad) {
    int idx = blockIdx.x * 256 + threadIdx.x;
    if (idx >= 128 * 260) return;
    int k = idx / 260, j = idx % 260;
    float v;
    if (j < 128)       v = W[k * 128 + j];
    else if (j < 256)  v = lw[k * 128 + (j - 128)];
    else {
        int t = j - 256;
        int hh = t & 1;
        const float* a = (t < 2) ? as : ad;
        float s = 0.f;
        for (int f = 0; f < 64; f++) s += W[k * 128 + hh * 64 + f] * a[hh * 64 + f];
        v = s;
    }
    if (j < 256) {
        __nv_bfloat16 h = __float2bfloat16(v);
        g_Bhi[l][j * 128 + k] = h;
        g_Blo[l][j * 128 + k] = __float2bfloat16(v - __bfloat162float(h));
        if (k == 0) g_bcatL[l][j] = (j >= 128) ? lb[j - 128] : 0.f;
    } else {
        g_wesd[l][k * 4 + (j - 256)] = v;
    }
}

// ---------------- mma / async helpers ----------------
__device__ __forceinline__ uint32_t smem_u32(const void* p) {
    uint32_t a;
    asm("{ .reg .u64 t; cvta.to.shared.u64 t, %1; cvt.u32.u64 %0, t; }" : "=r"(a) : "l"(p));
    return a;
}
__device__ __forceinline__ void cp_async16(uint32_t saddr, const void* g) {
    asm volatile("cp.async.cg.shared.global [%0], [%1], 16;" :: "r"(saddr), "l"(g));
}
#define CP_COMMIT() asm volatile("cp.async.commit_group;" ::: "memory")
#define CP_WAIT0()  asm volatile("cp.async.wait_group 0;" ::: "memory")
__device__ __forceinline__ void ldsm_x4(uint32_t* r, uint32_t addr) {
    asm volatile("ldmatrix.sync.aligned.m8n8.x4.shared.b16 {%0,%1,%2,%3}, [%4];"
        : "=r"(r[0]), "=r"(r[1]), "=r"(r[2]), "=r"(r[3]) : "r"(addr));
}
__device__ __forceinline__ void ldsm_x2(uint32_t* r, uint32_t addr) {
    asm volatile("ldmatrix.sync.aligned.m8n8.x2.shared.b16 {%0,%1}, [%2];"
        : "=r"(r[0]), "=r"(r[1]) : "r"(addr));
}
__device__ __forceinline__ void mma_bf16(float* d, const uint32_t* a, const uint32_t* b) {
    asm volatile("mma.sync.aligned.m16n8k16.row.col.f32.bf16.bf16.f32 "
        "{%0,%1,%2,%3}, {%4,%5,%6,%7}, {%8,%9}, {%0,%1,%2,%3};"
        : "+f"(d[0]), "+f"(d[1]), "+f"(d[2]), "+f"(d[3])
        : "r"(a[0]), "r"(a[1]), "r"(a[2]), "r"(a[3]), "r"(b[0]), "r"(b[1]));
}
__device__ __forceinline__ float leaky(float x) { return (x > 0.f) ? x : LEAKY * x; }

// ---------------- tensor-core GEMM v2: 1 CTA per 128 rows, full N=256, cp.async B --
#define APAD 136
#define TILE_BYTES (128 * APAD * 2)                 /* 34816 */
#define OFF_AHI  0
#define OFF_ALO  TILE_BYTES
#define OFF_BHI  (2 * TILE_BYTES)                   /* 256 rows: 2*TILE_BYTES */
#define OFF_BLO  (4 * TILE_BYTES)
#define OFF_WESD (6 * TILE_BYTES)
#define GEMM_SMEM (6 * TILE_BYTES + 2048)           /* 210944 */

__global__ __launch_bounds__(256, 1) void k_gemm_mma(int l, const float* __restrict__ Ain, int M) {
    const float* A = Ain ? Ain : g_H;
    extern __shared__ char sm[];
    __nv_bfloat16* sAhi = (__nv_bfloat16*)(sm + OFF_AHI);
    __nv_bfloat16* sAlo = (__nv_bfloat16*)(sm + OFF_ALO);
    __nv_bfloat16* sBhi = (__nv_bfloat16*)(sm + OFF_BHI);
    __nv_bfloat16* sBlo = (__nv_bfloat16*)(sm + OFF_BLO);
    float* wesd = (float*)(sm + OFF_WESD);

    int tid = threadIdx.x, lane = tid & 31, wid = tid >> 5;
    int warp_m = wid & 1;
    int warp_n = wid >> 1;
    int m0 = blockIdx.x * 128;

    // ---- B: fire-and-forget cp.async (raw bf16 copy, 32 chunks/thread) ----
    {
        uint32_t bhiBase = smem_u32(sBhi), bloBase = smem_u32(sBlo);
        const __nv_bfloat16* GH = g_Bhi[l];
        const __nv_bfloat16* GL = g_Blo[l];
#pragma unroll
        for (int p = 0; p < 16; p++) {
            int c2 = p * 256 + tid;                 // 0..4095
            int row = c2 >> 4, col = (c2 & 15) * 8;
            uint32_t soff = (uint32_t)(row * APAD + col) * 2;
            cp_async16(bhiBase + soff, GH + row * 128 + col);
            cp_async16(bloBase + soff, GL + row * 128 + col);
        }
        CP_COMMIT();
    }

    // ---- A: register-prefetch staging (2 batches of 8 float4) ----
#pragma unroll
    for (int b = 0; b < 2; b++) {
        float4 t[8];
#pragma unroll
        for (int i = 0; i < 8; i++) {
            int idx = (b * 8 + i) * 256 + tid;      // 0..4095
            int row = idx >> 5, c = (idx & 31) * 4;
            int gm = m0 + row;
            t[i] = (gm < M) ? *(const float4*)(A + gm * 128 + c)
                            : make_float4(0.f, 0.f, 0.f, 0.f);
        }
#pragma unroll
        for (int i = 0; i < 8; i++) {
            int idx = (b * 8 + i) * 256 + tid;
            int row = idx >> 5, c = (idx & 31) * 4;
            float v0 = t[i].x * g_scale[c]     + g_shift[c];
            float v1 = t[i].y * g_scale[c + 1] + g_shift[c + 1];
            float v2 = t[i].z * g_scale[c + 2] + g_shift[c + 2];
            float v3 = t[i].w * g_scale[c + 3] + g_shift[c + 3];
            __nv_bfloat16 h0 = __float2bfloat16(v0), h1 = __float2bfloat16(v1);
            __nv_bfloat16 h2 = __float2bfloat16(v2), h3 = __float2bfloat16(v3);
            int o = row * APAD + c;
            *(__nv_bfloat162*)(sAhi + o)     = __nv_bfloat162(h0, h1);
            *(__nv_bfloat162*)(sAhi + o + 2) = __nv_bfloat162(h2, h3);
            *(__nv_bfloat162*)(sAlo + o) =
                __nv_bfloat162(__float2bfloat16(v0 - __bfloat162float(h0)),
                               __float2bfloat16(v1 - __bfloat162float(h1)));
            *(__nv_bfloat162*)(sAlo + o + 2) =
                __nv_bfloat162(__float2bfloat16(v2 - __bfloat162float(h2)),
                               __float2bfloat16(v3 - __bfloat162float(h3)));
        }
    }
    for (int i = tid; i < 512; i += 256) wesd[i] = g_wesd[l][i];
    CP_WAIT0();
    __syncthreads();

    // ---- fused esd (4 attention cols) from staged A ----
    {
        for (int r = 0; r < 16; r++) {
            int row = wid * 16 + r;
            int gm = m0 + row;
            int k = lane * 4;
            int o = row * APAD + k;
            float a0 = __bfloat162float(sAhi[o])     + __bfloat162float(sAlo[o]);
            float a1 = __bfloat162float(sAhi[o + 1]) + __bfloat162float(sAlo[o + 1]);
            float a2 = __bfloat162float(sAhi[o + 2]) + __bfloat162float(sAlo[o + 2]);
            float a3 = __bfloat162float(sAhi[o + 3]) + __bfloat162float(sAlo[o + 3]);
            float s0 = a0 * wesd[k * 4]     + a1 * wesd[(k + 1) * 4]     + a2 * wesd[(k + 2) * 4]     + a3 * wesd[(k + 3) * 4];
            float s1 = a0 * wesd[k * 4 + 1] + a1 * wesd[(k + 1) * 4 + 1] + a2 * wesd[(k + 2) * 4 + 1] + a3 * wesd[(k + 3) * 4 + 1];
            float s2 = a0 * wesd[k * 4 + 2] + a1 * wesd[(k + 1) * 4 + 2] + a2 * wesd[(k + 2) * 4 + 2] + a3 * wesd[(k + 3) * 4 + 2];
            float s3 = a0 * wesd[k * 4 + 3] + a1 * wesd[(k + 1) * 4 + 3] + a2 * wesd[(k + 2) * 4 + 3] + a3 * wesd[(k + 3) * 4 + 3];
#pragma unroll
            for (int sh = 16; sh > 0; sh >>= 1) {
                s0 += __shfl_xor_sync(0xffffffffu, s0, sh);
                s1 += __shfl_xor_sync(0xffffffffu, s1, sh);
                s2 += __shfl_xor_sync(0xffffffffu, s2, sh);
                s3 += __shfl_xor_sync(0xffffffffu, s3, sh);
            }
            if (lane == 0 && gm < M) {
                g_ESDs[gm] = make_float2(s0, s1);
                g_ESDd[gm] = make_float2(s2, s3);
            }
        }
    }

    // ---- A ldsm bases (fixed across halves) ----
    int rA = lane & 15, cA = (lane >> 4) * 8;
    int rB = lane & 7,  cB = ((lane >> 3) & 1) * 8;
    uint32_t baseAhi[4], baseAlo[4];
#pragma unroll
    for (int mt = 0; mt < 4; mt++) {
        int row = warp_m * 64 + mt * 16 + rA;
        baseAhi[mt] = smem_u32(sAhi + row * APAD + cA);
        baseAlo[mt] = smem_u32(sAlo + row * APAD + cA);
    }

    // ---- two output halves ----
#pragma unroll
    for (int half = 0; half < 2; half++) {
        uint32_t baseBhi[4], baseBlo[4];
#pragma unroll
        for (int nt = 0; nt < 4; nt++) {
            int row = half * 128 + warp_n * 32 + nt * 8 + rB;
            baseBhi[nt] = smem_u32(sBhi + row * APAD + cB);
            baseBlo[nt] = smem_u32(sBlo + row * APAD + cB);
        }

        float acc[4][4][4] = {};
#pragma unroll
        for (int ks = 0; ks < 8; ks++) {
            uint32_t koff = ks * 32;
            uint32_t ahi[4][4], alo[4][4], bhi[4][2], blo[4][2];
#pragma unroll
            for (int mt = 0; mt < 4; mt++) {
                ldsm_x4(ahi[mt], baseAhi[mt] + koff);
                ldsm_x4(alo[mt], baseAlo[mt] + koff);
            }
#pragma unroll
            for (int nt = 0; nt < 4; nt++) {
                ldsm_x2(bhi[nt], baseBhi[nt] + koff);
                ldsm_x2(blo[nt], baseBlo[nt] + koff);
            }
#pragma unroll
            for (int mt = 0; mt < 4; mt++)
#pragma unroll
                for (int nt = 0; nt < 4; nt++) {
                    mma_bf16(acc[mt][nt], ahi[mt], bhi[nt]);
                    mma_bf16(acc[mt][nt], ahi[mt], blo[nt]);
                    mma_bf16(acc[mt][nt], alo[mt], bhi[nt]);
                }
        }

        // epilogue for this half
#pragma unroll
        for (int mt = 0; mt < 4; mt++) {
            int gm0 = m0 + warp_m * 64 + mt * 16 + (lane >> 2);
#pragma unroll
            for (int nt = 0; nt < 4; nt++) {
                int col = warp_n * 32 + nt * 8 + (lane & 3) * 2;
                float b0 = g_bcatL[l][half * 128 + col];
                float b1 = g_bcatL[l][half * 128 + col + 1];
                if (half == 0) {
                    if (gm0 < M)
                        *(__half2*)(g_HWh + gm0 * 128 + col) =
                            __floats2half2_rn(acc[mt][nt][0] + b0, acc[mt][nt][1] + b1);
                    if (gm0 + 8 < M)
                        *(__half2*)(g_HWh + (gm0 + 8) * 128 + col) =
                            __floats2half2_rn(acc[mt][nt][2] + b0, acc[mt][nt][3] + b1);
                } else {
                    if (gm0 < M) {
                        float2 v = {acc[mt][nt][0] + b0, acc[mt][nt][1] + b1};
                        *(float2*)(g_HL + gm0 * 128 + col) = v;
                    }
                    if (gm0 + 8 < M) {
                        float2 v = {acc[mt][nt][2] + b0, acc[mt][nt][3] + b1};
                        *(float2*)(g_HL + (gm0 + 8) * 128 + col) = v;
                    }
                }
            }
        }
    }
}

// ---------------- layer 3 GEMV ----------------
__global__ __launch_bounds__(256) void k_gemv6(const float* __restrict__ W3,
                                               const float* __restrict__ lw3,
                                               const float* __restrict__ lb3,
                                               const float* __restrict__ as3,
                                               const float* __restrict__ ad3,
                                               int n) {
    const float* A = g_H;
    __shared__ float ws[768];
    __shared__ float bs[8];
    int tid = threadIdx.x;
    for (int i = tid; i < 768; i += 256) {
        int k = i / 6, j = i % 6;
        float v;
        if (j < 2)      v = W3[k * 2 + j];
        else if (j < 4) v = lw3[k * 2 + (j - 2)];
        else {
            const float* a = (j == 4) ? as3 : ad3;
            v = W3[k * 2] * a[0] + W3[k * 2 + 1] * a[1];
        }
        ws[i] = v;
    }
    if (tid < 2) bs[tid] = lb3[tid];
    __syncthreads();
    int row = blockIdx.x * 8 + (tid >> 5);
    int lane = tid & 31;
    if (row >= n) return;
    float4 a = ((const float4*)A)[row * 32 + lane];
    int k = lane * 4;
    float a0 = a.x * g_scale[k]     + g_shift[k];
    float a1 = a.y * g_scale[k + 1] + g_shift[k + 1];
    float a2 = a.z * g_scale[k + 2] + g_shift[k + 2];
    float a3 = a.w * g_scale[k + 3] + g_shift[k + 3];
    float c[6];
#pragma unroll
    for (int j = 0; j < 6; j++)
        c[j] = a0 * ws[k * 6 + j] + a1 * ws[(k + 1) * 6 + j] +
               a2 * ws[(k + 2) * 6 + j] + a3 * ws[(k + 3) * 6 + j];
#pragma unroll
    for (int j = 0; j < 6; j++)
#pragma unroll
        for (int o = 16; o > 0; o >>= 1) c[j] += __shfl_xor_sync(0xffffffffu, c[j], o);
    if (lane == 0) {
        g_HW[row * 2]     = c[0];
        g_HW[row * 2 + 1] = c[1];
        g_HL[row * 2]     = c[2] + bs[0];
        g_HL[row * 2 + 1] = c[3] + bs[1];
        g_ESDs[row] = make_float2(c[4], 0.f);
        g_ESDd[row] = make_float2(c[5], 0.f);
    }
}

// ---------------- GAT edge phase, layers 1/2 ----------------
__global__ __launch_bounds__(256) void k_gat_edge12(const float* __restrict__ gb, int n) {
    int warp = (blockIdx.x * 256 + threadIdx.x) >> 5;
    int lane = threadIdx.x & 31;
    if (warp >= n) return;
    int node = warp;
    int beg = g_off[node], end = g_off[node + 1];
    float2 ed = g_ESDd[node];
    const uint2* HWh2 = (const uint2*)g_HWh;

    float sum0 = 0.f, sum1 = 0.f;
    float ax = 0.f, ay = 0.f, az = 0.f, aw = 0.f;
    for (int base = beg; base < end; base += 32) {
        int i = base + lane;
        int s = 0;
        float p0 = 0.f, p1 = 0.f;
        if (i < end) {
            s = g_csr[i];
            float2 e = g_ESDs[s];
            p0 = __expf(leaky(e.x + ed.x));
            p1 = __expf(leaky(e.y + ed.y));
        }
        sum0 += p0; sum1 += p1;
        __half2 ph2 = __floats2half2_rn(p0, p1);
        uint32_t ppack = *(uint32_t*)&ph2;
        int cnt = min(32, end - base);
        if (cnt == 32) {
#pragma unroll
            for (int j = 0; j < 32; j++) {
                int sj    = __shfl_sync(0xffffffffu, s, j);
                uint32_t qp = __shfl_sync(0xffffffffu, ppack, j);
                float2 pq = __half22float2(*(__half2*)&qp);
                float ph = (lane < 16) ? pq.x : pq.y;
                uint2 hv = HWh2[sj * 32 + lane];
                float2 f01 = __half22float2(*(__half2*)&hv.x);
                float2 f23 = __half22float2(*(__half2*)&hv.y);
                ax += ph * f01.x; ay += ph * f01.y; az += ph * f23.x; aw += ph * f23.y;
            }
        } else {
            for (int j = 0; j < cnt; j++) {
                int sj    = __shfl_sync(0xffffffffu, s, j);
                uint32_t qp = __shfl_sync(0xffffffffu, ppack, j);
                float2 pq = __half22float2(*(__half2*)&qp);
                float ph = (lane < 16) ? pq.x : pq.y;
                uint2 hv = HWh2[sj * 32 + lane];
                float2 f01 = __half22float2(*(__half2*)&hv.x);
                float2 f23 = __half22float2(*(__half2*)&hv.y);
                ax += ph * f01.x; ay += ph * f01.y; az += ph * f23.x; aw += ph * f23.y;
            }
        }
    }
#pragma unroll
    for (int o = 16; o > 0; o >>= 1) {
        sum0 += __shfl_xor_sync(0xffffffffu, sum0, o);
        sum1 += __shfl_xor_sync(0xffffffffu, sum1, o);
    }
    float inv = 1.f / ((lane < 16) ? sum0 : sum1);

    float4 hl = ((const float4*)g_HL)[node * 32 + lane];
    float4 gv = ((const float4*)gb)[lane];
    float4 o4;
    o4.x = fmaxf(hl.x + gv.x + ax * inv, 0.f);
    o4.y = fmaxf(hl.y + gv.y + ay * inv, 0.f);
    o4.z = fmaxf(hl.z + gv.z + az * inv, 0.f);
    o4.w = fmaxf(hl.w + gv.w + aw * inv, 0.f);
    ((float4*)g_H)[node * 32 + lane] = o4;
}

// ---------------- GAT edge phase, layer 3 ----------------
__global__ __launch_bounds__(256) void k_gat_edge3(const float* __restrict__ gb3,
                                                   float* __restrict__ out, int n) {
    int warp = (blockIdx.x * 256 + threadIdx.x) >> 5;
    int lane = threadIdx.x & 31;
    if (warp >= n) return;
    int node = warp;
    int beg = g_off[node], end = g_off[node + 1];
    float edv = g_ESDd[node].x;
    const float2* HW2 = (const float2*)g_HW;

    float sum = 0.f, a0 = 0.f, a1 = 0.f;
    for (int i = beg + lane; i < end; i += 32) {
        int s = g_csr[i];
        float p = __expf(leaky(g_ESDs[s].x + edv));
        float2 h = HW2[s];
        sum += p;
        a0 += p * h.x;
        a1 += p * h.y;
    }
#pragma unroll
    for (int o = 16; o > 0; o >>= 1) {
        sum += __shfl_xor_sync(0xffffffffu, sum, o);
        a0  += __shfl_xor_sync(0xffffffffu, a0, o);
        a1  += __shfl_xor_sync(0xffffffffu, a1, o);
    }
    if (lane == 0) {
        float inv = 1.f / sum;
        out[node * 2]     = fmaxf(g_HL[node * 2]     + gb3[0] + a0 * inv, 0.f);
        out[node * 2 + 1] = fmaxf(g_HL[node * 2 + 1] + gb3[1] + a1 * inv, 0.f);
    }
}

// ---------------- host launch ----------------
extern "C" void kernel_launch(void* const* d_in, const int* in_sizes, int n_in,
                              void* d_out, int out_size) {
    const float* x  = (const float*)d_in[0];
    const int*   ei = (const int*)d_in[1];
    const float *W1 = (const float*)d_in[2],  *as1 = (const float*)d_in[3],
                *ad1 = (const float*)d_in[4], *gb1 = (const float*)d_in[5],
                *lw1 = (const float*)d_in[6], *lb1 = (const float*)d_in[7],
                *bg1 = (const float*)d_in[8], *bb1 = (const float*)d_in[9];
    const float *W2 = (const float*)d_in[10], *as2 = (const float*)d_in[11],
                *ad2 = (const float*)d_in[12], *gb2 = (const float*)d_in[13],
                *lw2 = (const float*)d_in[14], *lb2 = (const float*)d_in[15],
                *bg2 = (const float*)d_in[16], *bb2 = (const float*)d_in[17];
    const float *W3 = (const float*)d_in[18], *as3 = (const float*)d_in[19],
                *ad3 = (const float*)d_in[20], *gb3 = (const float*)d_in[21],
                *lw3 = (const float*)d_in[22], *lb3 = (const float*)d_in[23],
                *bg3 = (const float*)d_in[24], *bb3 = (const float*)d_in[25];
    (void)n_in; (void)out_size;

    int n  = in_sizes[0] / 128;
    int E  = in_sizes[1] / 2;
    int ET = E + n;
    float* out = (float*)d_out;
    float inv_n = 1.f / (float)n;

    int eb = (ET + 255) / 256;
    int gg = (n + 127) / 128;
    int wb = (n + 7) / 8;

    static int inited = 0;
    static cudaStream_t s1 = nullptr, s2 = nullptr;
    static cudaEvent_t ev_fork = nullptr, ev_p1 = nullptr, ev_p2 = nullptr, ev_csr = nullptr;
    if (!inited) {
        cudaFuncSetAttribute(k_gemm_mma, cudaFuncAttributeMaxDynamicSharedMemorySize, GEMM_SMEM);
        cudaStreamCreateWithFlags(&s1, cudaStreamNonBlocking);
        cudaStreamCreateWithFlags(&s2, cudaStreamNonBlocking);
        cudaEventCreateWithFlags(&ev_fork, cudaEventDisableTiming);
        cudaEventCreateWithFlags(&ev_p1, cudaEventDisableTiming);
        cudaEventCreateWithFlags(&ev_p2, cudaEventDisableTiming);
        cudaEventCreateWithFlags(&ev_csr, cudaEventDisableTiming);
        inited = 1;
    }

    // ---- fork side streams ----
    cudaEventRecord(ev_fork, 0);
    cudaStreamWaitEvent(s1, ev_fork, 0);
    cudaStreamWaitEvent(s2, ev_fork, 0);

    // launch 1: edge count
    k_count<<<eb, 256, 0, s2>>>(ei, E, ET);

    // launch 2: layer-1 weight prep
    k_prep12<<<131, 256, 0, s1>>>(0, W1, lw1, lb1, as1, ad1);
    cudaEventRecord(ev_p1, s1);

    // launch 3: layer-1 BN stats (main)
    k_bnr<<<NSM, 1024>>>(x, n * 128, bg1, bb1, inv_n, NSM);

    // launch 4: layer-1 GEMM (main)  <-- profiled by ncu
    cudaStreamWaitEvent(0, ev_p1, 0);
    k_gemm_mma<<<gg, 256, GEMM_SMEM>>>(0, x, n);

    // launches 5-6: CSR scan + scatter (s2)
    k_scan<<<NSM, 256, 0, s2>>>(n, NSM);
    k_scatter<<<eb, 256, 0, s2>>>(ei, E, ET);
    cudaEventRecord(ev_csr, s2);

    // launch 7: layer-2 weight prep (s1)
    k_prep12<<<131, 256, 0, s1>>>(1, W2, lw2, lb2, as2, ad2);
    cudaEventRecord(ev_p2, s1);

    // launch 8: layer-1 edge phase (main)
    cudaStreamWaitEvent(0, ev_csr, 0);
    k_gat_edge12<<<wb, 256>>>(gb1, n);

    // layer 2
    k_bnr<<<NSM, 1024>>>(nullptr, n * 128, bg2, bb2, inv_n, NSM);
    cudaStreamWaitEvent(0, ev_p2, 0);
    k_gemm_mma<<<gg, 256, GEMM_SMEM>>>(1, nullptr, n);
    k_gat_edge12<<<wb, 256>>>(gb2, n);

    // layer 3
    k_bnr<<<NSM, 1024>>>(nullptr, n * 128, bg3, bb3, inv_n, NSM);
    k_gemv6<<<wb, 256>>>(W3, lw3, lb3, as3, ad3, n);
    k_gat_edge3<<<wb, 256>>>(gb3, out, n);
}